// round 1
// baseline (speedup 1.0000x reference)
#include <cuda_runtime.h>
#include <math.h>

#define CONVK 4608   // 512 * 9

// ---------------- scratch buffers (device globals; no allocations allowed) ----
__device__ float g_x[512 * 1024];          // current token features (C, N)
__device__ float g_qkv[1536 * 1024];       // qkv (3C, N): rows j = s*512 + h*64 + d
__device__ float g_S[8 * 1024 * 1024];     // attention scores (h, n, m)
__device__ float g_att[512 * 1024];        // attention output (C, N)
__device__ float g_h[512 * 2500];          // EDSR head output (kept for skip)
__device__ float g_b0[512 * 10000];        // generic activation buffers
__device__ float g_b1[512 * 10000];
__device__ float g_b2[512 * 10000];        // also holds up-conv output (2048*2500)

// ---------------- generic tiled GEMM: C = alpha*op(A)*op(B) (+bias) (+resid) --
// Tile 64x64, K-step 16, 256 threads, 4x4 micro-tile per thread.
// transA: A stored (K x M) with leading dim lda. transB: B stored (N x K).
__global__ void gemm_kernel(
    const float* __restrict__ A, int lda, int transA, long long strideA,
    const float* __restrict__ B, int ldb, int transB, long long strideB,
    float* __restrict__ Cm, int ldc, long long strideC,
    int M, int N, int K, float alpha,
    const float* __restrict__ bias,
    const float* __restrict__ resid, int ldres)
{
    int bz = blockIdx.z;
    A += (long long)bz * strideA;
    B += (long long)bz * strideB;
    Cm += (long long)bz * strideC;
    if (resid) resid += (long long)bz * strideC;  // resid stride == C stride when batched

    __shared__ float As[16][64];
    __shared__ float Bs[16][64];

    int tid = threadIdx.x;
    int tx = tid & 15, ty = tid >> 4;
    int m0 = blockIdx.y * 64, n0 = blockIdx.x * 64;

    float acc[4][4] = {};

    for (int k0 = 0; k0 < K; k0 += 16) {
        if (!transA) {
            #pragma unroll
            for (int s = 0; s < 4; s++) {
                int idx = tid + s * 256;
                int m = idx >> 4, k = idx & 15;
                float v = 0.f;
                if (m0 + m < M && k0 + k < K) v = A[(long long)(m0 + m) * lda + k0 + k];
                As[k][m] = v;
            }
        } else {
            #pragma unroll
            for (int s = 0; s < 4; s++) {
                int idx = tid + s * 256;
                int m = idx & 63, k = idx >> 6;
                float v = 0.f;
                if (m0 + m < M && k0 + k < K) v = A[(long long)(k0 + k) * lda + m0 + m];
                As[k][m] = v;
            }
        }
        if (!transB) {
            #pragma unroll
            for (int s = 0; s < 4; s++) {
                int idx = tid + s * 256;
                int n = idx & 63, k = idx >> 6;
                float v = 0.f;
                if (n0 + n < N && k0 + k < K) v = B[(long long)(k0 + k) * ldb + n0 + n];
                Bs[k][n] = v;
            }
        } else {
            #pragma unroll
            for (int s = 0; s < 4; s++) {
                int idx = tid + s * 256;
                int k = idx & 15, n = idx >> 4;
                float v = 0.f;
                if (n0 + n < N && k0 + k < K) v = B[(long long)(n0 + n) * ldb + k0 + k];
                Bs[k][n] = v;
            }
        }
        __syncthreads();
        #pragma unroll
        for (int k = 0; k < 16; k++) {
            float4 a = *(const float4*)&As[k][ty * 4];
            float4 b = *(const float4*)&Bs[k][tx * 4];
            float av[4] = {a.x, a.y, a.z, a.w};
            float bv[4] = {b.x, b.y, b.z, b.w};
            #pragma unroll
            for (int i = 0; i < 4; i++)
                #pragma unroll
                for (int j = 0; j < 4; j++)
                    acc[i][j] = fmaf(av[i], bv[j], acc[i][j]);
        }
        __syncthreads();
    }

    #pragma unroll
    for (int i = 0; i < 4; i++) {
        int m = m0 + ty * 4 + i;
        if (m >= M) continue;
        float bsv = bias ? bias[m] : 0.f;
        #pragma unroll
        for (int j = 0; j < 4; j++) {
            int n = n0 + tx * 4 + j;
            if (n >= N) continue;
            float v = acc[i][j] * alpha + bsv;
            if (resid) v += resid[(long long)m * ldres + n];
            Cm[(long long)m * ldc + n] = v;
        }
    }
}

// ---------------- implicit-GEMM 3x3 conv (Ci fixed at 512, pad=1) -------------
// out[co][p] = sum_{k=(ci,ky,kx)} w[co][k] * in[ci][y+ky-1][x+kx-1]
// epilogue: +bias | BN(eval) | +resid | relu
__global__ void conv3x3_kernel(
    const float* __restrict__ in,   // (512, H, W)
    const float* __restrict__ w,    // (Co, 512, 3, 3) -> (Co, 4608) contiguous
    float* __restrict__ out,        // (Co, H, W)
    int Co, int H, int W,
    const float* __restrict__ bias,
    const float* __restrict__ bn_g, const float* __restrict__ bn_b,
    const float* __restrict__ bn_m, const float* __restrict__ bn_v,
    const float* __restrict__ resid,
    int relu)
{
    const int P = H * W;
    __shared__ float As[16][64];
    __shared__ float Bs[16][64];

    int tid = threadIdx.x;
    int tx = tid & 15, ty = tid >> 4;
    int m0 = blockIdx.y * 64, n0 = blockIdx.x * 64;

    // B-load slots: each thread owns one pixel, 4 k-offsets {base, base+4, base+8, base+12}
    int n_pix = tid & 63;
    int p = n0 + n_pix;
    bool pvalid = p < P;
    int yy = pvalid ? p / W : 0;
    int xx = pvalid ? p - yy * W : 0;
    int kbase = tid >> 6;

    float acc[4][4] = {};

    for (int k0 = 0; k0 < CONVK; k0 += 16) {
        // weights: coalesced row-major tile (Co x 16)
        #pragma unroll
        for (int s = 0; s < 4; s++) {
            int idx = tid + s * 256;
            int m = idx >> 4, kk = idx & 15;
            float v = 0.f;
            if (m0 + m < Co) v = w[(long long)(m0 + m) * CONVK + k0 + kk];
            As[kk][m] = v;
        }
        // input: gathered im2col tile (16 x 64 pixels)
        #pragma unroll
        for (int s = 0; s < 4; s++) {
            int koff = kbase + s * 4;
            int k = k0 + koff;
            int ci = k / 9;
            int tap = k - ci * 9;
            int t3 = tap / 3;
            int dy = t3 - 1, dx = tap - t3 * 3 - 1;
            int y2 = yy + dy, x2 = xx + dx;
            float v = 0.f;
            if (pvalid && (unsigned)y2 < (unsigned)H && (unsigned)x2 < (unsigned)W)
                v = in[(long long)ci * P + y2 * W + x2];
            Bs[koff][n_pix] = v;
        }
        __syncthreads();
        #pragma unroll
        for (int k = 0; k < 16; k++) {
            float4 a = *(const float4*)&As[k][ty * 4];
            float4 b = *(const float4*)&Bs[k][tx * 4];
            float av[4] = {a.x, a.y, a.z, a.w};
            float bv[4] = {b.x, b.y, b.z, b.w};
            #pragma unroll
            for (int i = 0; i < 4; i++)
                #pragma unroll
                for (int j = 0; j < 4; j++)
                    acc[i][j] = fmaf(av[i], bv[j], acc[i][j]);
        }
        __syncthreads();
    }

    #pragma unroll
    for (int i = 0; i < 4; i++) {
        int m = m0 + ty * 4 + i;
        if (m >= Co) continue;
        float bsv = bias ? bias[m] : 0.f;
        float sc = 1.f, sh = 0.f;
        if (bn_g) {
            float s = bn_g[m] * rsqrtf(bn_v[m] + 1e-5f);
            sc = s;
            sh = bn_b[m] - bn_m[m] * s;
        }
        #pragma unroll
        for (int j = 0; j < 4; j++) {
            int nn = n0 + tx * 4 + j;
            if (nn >= P) continue;
            float v = acc[i][j] + bsv;
            if (bn_g) v = v * sc + sh;
            if (resid) v += resid[(long long)m * P + nn];
            if (relu) v = fmaxf(v, 0.f);
            out[(long long)m * P + nn] = v;
        }
    }
}

// ---------------- softmax over last dim (one warp per row) --------------------
__global__ void softmax_rows(float* __restrict__ S, int rows, int cols)
{
    int warp = (blockIdx.x * blockDim.x + threadIdx.x) >> 5;
    int lane = threadIdx.x & 31;
    if (warp >= rows) return;
    float* row = S + (long long)warp * cols;
    float mx = -INFINITY;
    for (int i = lane; i < cols; i += 32) mx = fmaxf(mx, row[i]);
    #pragma unroll
    for (int o = 16; o; o >>= 1) mx = fmaxf(mx, __shfl_xor_sync(0xffffffffu, mx, o));
    float sum = 0.f;
    for (int i = lane; i < cols; i += 32) {
        float e = __expf(row[i] - mx);
        row[i] = e;
        sum += e;
    }
    #pragma unroll
    for (int o = 16; o; o >>= 1) sum += __shfl_xor_sync(0xffffffffu, sum, o);
    float inv = 1.f / sum;
    for (int i = lane; i < cols; i += 32) row[i] *= inv;
}

// ---------------- BEV grid transform: (512,32,32) -> (512,50,50) NN gather ----
// f = 0.625*j + 0.1875 (analytic; all indices land in [0,31], all valid)
__global__ void grid_sample_kernel(const float* __restrict__ in, float* __restrict__ out)
{
    int idx = blockIdx.x * blockDim.x + threadIdx.x;
    if (idx >= 512 * 50 * 50) return;
    int i = idx % 50;
    int j = (idx / 50) % 50;
    int c = idx / 2500;
    int iy = __float2int_rn(0.625f * (float)j + 0.1875f);
    int ix = __float2int_rn(0.625f * (float)i + 0.1875f);
    out[idx] = in[c * 1024 + iy * 32 + ix];
}

// ---------------- pixel shuffle r=2: (2048,50,50) -> (512,100,100) ------------
__global__ void pixel_shuffle_kernel(const float* __restrict__ in, float* __restrict__ out)
{
    int idx = blockIdx.x * blockDim.x + threadIdx.x;
    if (idx >= 512 * 100 * 100) return;
    int ox = idx % 100;
    int oy = (idx / 100) % 100;
    int c = idx / 10000;
    int y = oy >> 1, ry = oy & 1;
    int x = ox >> 1, rx = ox & 1;
    out[idx] = in[(c * 4 + ry * 2 + rx) * 2500 + y * 50 + x];
}

// ---------------- final 1x1 conv (512 -> 6) + sigmoid -------------------------
__global__ void conv1x1_sigmoid_kernel(
    const float* __restrict__ in, const float* __restrict__ w,
    const float* __restrict__ b, float* __restrict__ out)
{
    int idx = blockIdx.x * blockDim.x + threadIdx.x;  // 6 * 10000
    if (idx >= 6 * 10000) return;
    int p = idx % 10000;
    int cls = idx / 10000;
    float acc = b[cls];
    const float* wp = w + cls * 512;
    #pragma unroll 4
    for (int c = 0; c < 512; c++)
        acc = fmaf(in[c * 10000 + p], wp[c], acc);
    out[idx] = 1.f / (1.f + __expf(-acc));
}

__global__ void copy_kernel(const float* __restrict__ in, float* __restrict__ out, int n)
{
    int i = blockIdx.x * blockDim.x + threadIdx.x;
    if (i < n) out[i] = in[i];
}

// ---------------- host orchestration -----------------------------------------
static inline dim3 tile_grid(int M, int N, int Z)
{
    return dim3((unsigned)((N + 63) / 64), (unsigned)((M + 63) / 64), (unsigned)Z);
}

static void launch_conv(const float* in, const float* w, float* out, int Co, int H, int W,
                        const float* bias,
                        const float* g, const float* bb, const float* m, const float* v,
                        const float* res, int relu)
{
    conv3x3_kernel<<<tile_grid(Co, H * W, 1), 256>>>(in, w, out, Co, H, W,
                                                     bias, g, bb, m, v, res, relu);
}

extern "C" void kernel_launch(void* const* d_in, const int* in_sizes, int n_in,
                              void* d_out, int out_size)
{
    const float* x       = (const float*)d_in[0];
    const float* qkv_w   = (const float*)d_in[1];
    const float* proj_w  = (const float*)d_in[2];
    const float* proj_b  = (const float*)d_in[3];
    const float* head_w  = (const float*)d_in[4];
    const float* head_b  = (const float*)d_in[5];
    const float* body_w  = (const float*)d_in[6];
    const float* body_b  = (const float*)d_in[7];
    const float* btail_w = (const float*)d_in[8];
    const float* btail_b = (const float*)d_in[9];
    const float* up_w    = (const float*)d_in[10];
    const float* up_b    = (const float*)d_in[11];
    const float* tail_w  = (const float*)d_in[12];
    const float* tail_b  = (const float*)d_in[13];
    const float* c1_w    = (const float*)d_in[14];
    const float* bn1_g   = (const float*)d_in[15];
    const float* bn1_b   = (const float*)d_in[16];
    const float* bn1_m   = (const float*)d_in[17];
    const float* bn1_v   = (const float*)d_in[18];
    const float* c2_w    = (const float*)d_in[19];
    const float* bn2_g   = (const float*)d_in[20];
    const float* bn2_b   = (const float*)d_in[21];
    const float* bn2_m   = (const float*)d_in[22];
    const float* bn2_v   = (const float*)d_in[23];
    const float* c3_w    = (const float*)d_in[24];
    const float* c3_b    = (const float*)d_in[25];

    float *gx, *gqkv, *gS, *gatt, *gh, *b0, *b1, *b2;
    cudaGetSymbolAddress((void**)&gx,   g_x);
    cudaGetSymbolAddress((void**)&gqkv, g_qkv);
    cudaGetSymbolAddress((void**)&gS,   g_S);
    cudaGetSymbolAddress((void**)&gatt, g_att);
    cudaGetSymbolAddress((void**)&gh,   g_h);
    cudaGetSymbolAddress((void**)&b0,   g_b0);
    cudaGetSymbolAddress((void**)&b1,   g_b1);
    cudaGetSymbolAddress((void**)&b2,   g_b2);

    // x -> working buffer (C=512, N=1024)
    copy_kernel<<<(512 * 1024 + 255) / 256, 256>>>(x, gx, 512 * 1024);

    const float scale = 0.044194173824159216f;  // 512^-0.5

    // ---- 8 self-attention blocks ----
    for (int i = 0; i < 8; i++) {
        // qkv^T (3C, N) = qkv_w_i^T (transA) @ x (C, N)
        gemm_kernel<<<tile_grid(1536, 1024, 1), 256>>>(
            qkv_w + (long long)i * 512 * 1536, 1536, 1, 0,
            gx, 1024, 0, 0,
            gqkv, 1024, 0,
            1536, 1024, 512, 1.f, nullptr, nullptr, 0);

        // S[h](n,m) = scale * q_h^T @ k_h ;  q_h/k_h are (64, N) row blocks of gqkv
        gemm_kernel<<<tile_grid(1024, 1024, 8), 256>>>(
            gqkv, 1024, 1, 64 * 1024,                       // A = q (K=64 x M=1024 storage)
            gqkv + 512 * 1024, 1024, 0, 64 * 1024,          // B = k
            gS, 1024, 1024 * 1024,
            1024, 1024, 64, scale, nullptr, nullptr, 0);

        softmax_rows<<<1024, 256>>>(gS, 8 * 1024, 1024);

        // att[h*64+d][n] = v_h (64 x 1024) @ P_h^T (transB: stored (n, m))
        gemm_kernel<<<tile_grid(64, 1024, 8), 256>>>(
            gqkv + 1024 * 1024, 1024, 0, 64 * 1024,         // A = v
            gS, 1024, 1, 1024 * 1024,                       // B = P (transB)
            gatt, 1024, 64 * 1024,
            64, 1024, 1024, 1.f, nullptr, nullptr, 0);

        // x += proj_w_i^T @ att + proj_b_i   (in-place residual)
        gemm_kernel<<<tile_grid(512, 1024, 1), 256>>>(
            proj_w + (long long)i * 512 * 512, 512, 1, 0,
            gatt, 1024, 0, 0,
            gx, 1024, 0,
            512, 1024, 512, 1.f, proj_b + i * 512, gx, 1024);
    }

    // ---- BEV grid transform: (512,32,32) -> (512,50,50) ----
    grid_sample_kernel<<<(512 * 2500 + 255) / 256, 256>>>(gx, b0);

    // ---- EDSR ----
    launch_conv(b0, head_w, gh, 512, 50, 50, head_b, 0, 0, 0, 0, nullptr, 0);
    const float* rcur = gh;
    float* bufs[2] = {b1, b2};
    for (int i = 0; i < 8; i++) {
        const float* w0 = body_w + (long long)i * 2 * 512 * CONVK;
        const float* w1 = w0 + (long long)512 * CONVK;
        launch_conv(rcur, w0, b0, 512, 50, 50, body_b + i * 1024, 0, 0, 0, 0, nullptr, 1);
        float* rnext = bufs[i & 1];
        launch_conv(b0, w1, rnext, 512, 50, 50, body_b + i * 1024 + 512, 0, 0, 0, 0, rcur, 0);
        rcur = rnext;
    }
    // rcur == b2 after 8 iterations
    launch_conv(rcur, btail_w, b1, 512, 50, 50, btail_b, 0, 0, 0, 0, gh, 0);
    launch_conv(b1, up_w, b2, 2048, 50, 50, up_b, 0, 0, 0, 0, nullptr, 0);
    pixel_shuffle_kernel<<<(512 * 10000 + 255) / 256, 256>>>(b2, b0);
    launch_conv(b0, tail_w, b1, 512, 100, 100, tail_b, 0, 0, 0, 0, nullptr, 0);

    // ---- classifier ----
    launch_conv(b1, c1_w, b0, 512, 100, 100, nullptr, bn1_g, bn1_b, bn1_m, bn1_v, nullptr, 1);
    launch_conv(b0, c2_w, b1, 512, 100, 100, nullptr, bn2_g, bn2_b, bn2_m, bn2_v, nullptr, 1);
    conv1x1_sigmoid_kernel<<<(6 * 10000 + 255) / 256, 256>>>(b1, c3_w, c3_b, (float*)d_out);
}

// round 3
// speedup vs baseline: 1.8802x; 1.8802x over previous
#include <cuda_runtime.h>
#include <cuda_bf16.h>
#include <math.h>
#include <stdint.h>

#define CONVK 4608   // 512 * 9

// ---------------- scratch buffers (device globals; no allocations allowed) ----
__device__ float g_x[512 * 1024];          // current token features (C, N)
__device__ float g_qkv[1536 * 1024];       // qkv (3C, N)
__device__ float g_S[8 * 1024 * 1024];     // attention scores (h, n, m)
__device__ float g_att[512 * 1024];        // attention output (C, N)
__device__ float g_h[512 * 2500];          // EDSR head output (skip)
__device__ float g_b0[512 * 10000];
__device__ float g_b1[512 * 10000];
__device__ float g_b2[512 * 10000];        // also holds up-conv output (2048*2500)

// =================== warp-MMA helpers (arch-neutral, run as HMMA) =============
__device__ __forceinline__ uint32_t smem_u32(const void* p) {
    uint32_t a;
    asm("{ .reg .u64 t; cvta.to.shared.u64 t, %1; cvt.u32.u64 %0, t; }" : "=r"(a) : "l"(p));
    return a;
}

__device__ __forceinline__ void ldsm_x4(uint32_t (&r)[4], uint32_t addr) {
    asm volatile("ldmatrix.sync.aligned.m8n8.x4.shared.b16 {%0,%1,%2,%3}, [%4];"
        : "=r"(r[0]), "=r"(r[1]), "=r"(r[2]), "=r"(r[3]) : "r"(addr));
}

__device__ __forceinline__ void mma16816(float* d, const uint32_t (&a)[4], const uint32_t* b) {
    asm volatile("mma.sync.aligned.m16n8k16.row.col.f32.bf16.bf16.f32 "
        "{%0,%1,%2,%3}, {%4,%5,%6,%7}, {%8,%9}, {%0,%1,%2,%3};"
        : "+f"(d[0]), "+f"(d[1]), "+f"(d[2]), "+f"(d[3])
        : "r"(a[0]), "r"(a[1]), "r"(a[2]), "r"(a[3]), "r"(b[0]), "r"(b[1]));
}

// fp32 -> (hi, lo) bf16 split, packed pairs
__device__ __forceinline__ void split2(float f0, float f1, uint32_t& hi, uint32_t& lo) {
    __nv_bfloat162 h = __floats2bfloat162_rn(f0, f1);
    float r0 = f0 - __bfloat162float(h.x);
    float r1 = f1 - __bfloat162float(h.y);
    __nv_bfloat162 l = __floats2bfloat162_rn(r0, r1);
    hi = *reinterpret_cast<uint32_t*>(&h);
    lo = *reinterpret_cast<uint32_t*>(&l);
}

__device__ __forceinline__ float fetch_in(const float* __restrict__ in, int k,
                                          int y, int x, bool pv, int H, int W, int P) {
    int ci = k / 9;
    int tap = k - ci * 9;
    int t3 = tap / 3;
    int dy = t3 - 1, dx = tap - t3 * 3 - 1;
    int y2 = y + dy, x2 = x + dx;
    if (pv && (unsigned)y2 < (unsigned)H && (unsigned)x2 < (unsigned)W)
        return in[ci * P + y2 * W + x2];
    return 0.f;
}

// =================== bf16-split implicit-GEMM 3x3 conv (mma.sync) =============
// CTA tile: 128 (Co) x 64 (pixels). K = 4608, chunks of 64.
// SMEM (dynamic 48KB): A_hi[16K] A_lo[16K] B_hi[8K] B_lo[8K], SW128-swizzled
// 128B rows (row*128 + col ^ ((row&7)<<4)).
// 3 passes per chunk: A_hi*B_hi + A_hi*B_lo + A_lo*B_hi, fp32 accumulators.
__global__ __launch_bounds__(256)
void conv3x3_mma(const float* __restrict__ in, const float* __restrict__ w,
                 float* __restrict__ out, int Co, int H, int W,
                 const float* __restrict__ bias,
                 const float* __restrict__ bn_g, const float* __restrict__ bn_b,
                 const float* __restrict__ bn_m, const float* __restrict__ bn_v,
                 const float* __restrict__ resid, int relu)
{
    constexpr uint32_t AHI = 0, ALO = 16384, BHI = 32768, BLO = 40960;
    extern __shared__ char sm[];
    const uint32_t sbase = smem_u32(sm);

    const int P = H * W;
    const int tid = threadIdx.x;
    const int lane = tid & 31;
    const int wid = tid >> 5;
    const int wm = wid >> 1;          // 0..3 : which 32-row block of M
    const int wn = wid & 1;           // 0..1 : which 32-col block of N
    const int m0 = blockIdx.y * 128;
    const int n0 = blockIdx.x * 64;

    // ---- per-lane ldmatrix address components ----
    const uint32_t xorv = (uint32_t)(lane & 7) << 4;
    const uint32_t a_cg = (uint32_t)(lane >> 4) << 4;            // 0 or 16
    const uint32_t b_cg = (uint32_t)((lane >> 3) & 1) << 4;      // 0 or 16
    uint32_t arow[2], brow[2];
    #pragma unroll
    for (int mt = 0; mt < 2; mt++)
        arow[mt] = (uint32_t)(wm * 32 + mt * 16 + (lane & 15)) * 128;
    const int b_r = wn * 32 + (lane & 7) + ((lane >> 4) * 8);
    #pragma unroll
    for (int nt = 0; nt < 2; nt++)
        brow[nt] = (uint32_t)(b_r + nt * 16) * 128;

    // ---- per-thread staging slots ----
    // B: 8 slots: pixel = idx&63, k-pair = idx>>6
    int pys[8], pxs[8]; bool pvs[8];
    #pragma unroll
    for (int s = 0; s < 8; s++) {
        int idx = s * 256 + tid;
        int pix = idx & 63;
        int p = n0 + pix;
        bool v = p < P;
        int y = v ? p / W : 0;
        pvs[s] = v; pys[s] = y; pxs[s] = v ? p - y * W : 0;
    }

    float acc[2][4][4] = {};

    #pragma unroll 1
    for (int c = 0; c < 72; c++) {
        const int k0 = c * 64;
        // ---- stage A (weights, coalesced float2) ----
        #pragma unroll
        for (int s = 0; s < 16; s++) {
            int idx = s * 256 + tid;
            int row = idx >> 5, pr = idx & 31;
            float2 f = *(const float2*)(w + (size_t)(m0 + row) * CONVK + k0 + pr * 2);
            uint32_t h, l; split2(f.x, f.y, h, l);
            uint32_t off = (uint32_t)row * 128 + (((uint32_t)pr * 4) ^ (((uint32_t)row & 7) << 4));
            *(uint32_t*)(sm + AHI + off) = h;
            *(uint32_t*)(sm + ALO + off) = l;
        }
        // ---- stage B (im2col gather) ----
        #pragma unroll
        for (int s = 0; s < 8; s++) {
            int idx = s * 256 + tid;
            int pix = idx & 63, pr = idx >> 6;
            int k = k0 + pr * 2;
            float f0 = fetch_in(in, k,     pys[s], pxs[s], pvs[s], H, W, P);
            float f1 = fetch_in(in, k + 1, pys[s], pxs[s], pvs[s], H, W, P);
            uint32_t h, l; split2(f0, f1, h, l);
            uint32_t off = (uint32_t)pix * 128 + (((uint32_t)pr * 4) ^ (((uint32_t)pix & 7) << 4));
            *(uint32_t*)(sm + BHI + off) = h;
            *(uint32_t*)(sm + BLO + off) = l;
        }
        __syncthreads();

        // ---- compute: 3 split passes x 4 k16 steps ----
        #pragma unroll
        for (int pass = 0; pass < 3; pass++) {
            const uint32_t ao = sbase + ((pass == 2) ? ALO : AHI);
            const uint32_t bo = sbase + ((pass == 1) ? BLO : BHI);
            #pragma unroll
            for (int kk = 0; kk < 4; kk++) {
                const uint32_t cbA = (((uint32_t)kk << 5) | a_cg) ^ xorv;
                const uint32_t cbB = (((uint32_t)kk << 5) | b_cg) ^ xorv;
                uint32_t a0[4], a1[4], b0[4], b1[4];
                ldsm_x4(a0, ao + arow[0] + cbA);
                ldsm_x4(a1, ao + arow[1] + cbA);
                ldsm_x4(b0, bo + brow[0] + cbB);
                ldsm_x4(b1, bo + brow[1] + cbB);
                mma16816(acc[0][0], a0, &b0[0]);
                mma16816(acc[0][1], a0, &b0[2]);
                mma16816(acc[0][2], a0, &b1[0]);
                mma16816(acc[0][3], a0, &b1[2]);
                mma16816(acc[1][0], a1, &b0[0]);
                mma16816(acc[1][1], a1, &b0[2]);
                mma16816(acc[1][2], a1, &b1[0]);
                mma16816(acc[1][3], a1, &b1[2]);
            }
        }
        __syncthreads();
    }

    // ---- epilogue: fragment layout c0,c1=(row,col..col+1), c2,c3=(row+8,..) ----
    #pragma unroll
    for (int mt = 0; mt < 2; mt++) {
        #pragma unroll
        for (int nt = 0; nt < 4; nt++) {
            int row = m0 + wm * 32 + mt * 16 + (lane >> 2);
            int col = n0 + wn * 32 + nt * 8 + (lane & 3) * 2;
            if (col >= P) continue;
            #pragma unroll
            for (int half = 0; half < 2; half++) {
                int r = row + half * 8;
                float v0 = acc[mt][nt][half * 2 + 0];
                float v1 = acc[mt][nt][half * 2 + 1];
                if (bias) { v0 += bias[r]; v1 += bias[r]; }
                if (bn_g) {
                    float sc = bn_g[r] * rsqrtf(bn_v[r] + 1e-5f);
                    float sh = bn_b[r] - bn_m[r] * sc;
                    v0 = v0 * sc + sh; v1 = v1 * sc + sh;
                }
                if (resid) {
                    float2 rr = *(const float2*)(resid + (size_t)r * P + col);
                    v0 += rr.x; v1 += rr.y;
                }
                if (relu) { v0 = fmaxf(v0, 0.f); v1 = fmaxf(v1, 0.f); }
                *(float2*)(out + (size_t)r * P + col) = make_float2(v0, v1);
            }
        }
    }
}

// =================== SIMT GEMM (attention path, unchanged) ====================
__global__ void gemm_kernel(
    const float* __restrict__ A, int lda, int transA, long long strideA,
    const float* __restrict__ B, int ldb, int transB, long long strideB,
    float* __restrict__ Cm, int ldc, long long strideC,
    int M, int N, int K, float alpha,
    const float* __restrict__ bias,
    const float* __restrict__ resid, int ldres)
{
    int bz = blockIdx.z;
    A += (long long)bz * strideA;
    B += (long long)bz * strideB;
    Cm += (long long)bz * strideC;
    if (resid) resid += (long long)bz * strideC;

    __shared__ float As[16][64];
    __shared__ float Bs[16][64];

    int tid = threadIdx.x;
    int tx = tid & 15, ty = tid >> 4;
    int m0 = blockIdx.y * 64, n0 = blockIdx.x * 64;

    float acc[4][4] = {};

    for (int k0 = 0; k0 < K; k0 += 16) {
        if (!transA) {
            #pragma unroll
            for (int s = 0; s < 4; s++) {
                int idx = tid + s * 256;
                int m = idx >> 4, k = idx & 15;
                float v = 0.f;
                if (m0 + m < M && k0 + k < K) v = A[(long long)(m0 + m) * lda + k0 + k];
                As[k][m] = v;
            }
        } else {
            #pragma unroll
            for (int s = 0; s < 4; s++) {
                int idx = tid + s * 256;
                int m = idx & 63, k = idx >> 6;
                float v = 0.f;
                if (m0 + m < M && k0 + k < K) v = A[(long long)(k0 + k) * lda + m0 + m];
                As[k][m] = v;
            }
        }
        if (!transB) {
            #pragma unroll
            for (int s = 0; s < 4; s++) {
                int idx = tid + s * 256;
                int n = idx & 63, k = idx >> 6;
                float v = 0.f;
                if (n0 + n < N && k0 + k < K) v = B[(long long)(k0 + k) * ldb + n0 + n];
                Bs[k][n] = v;
            }
        } else {
            #pragma unroll
            for (int s = 0; s < 4; s++) {
                int idx = tid + s * 256;
                int k = idx & 15, n = idx >> 4;
                float v = 0.f;
                if (n0 + n < N && k0 + k < K) v = B[(long long)(n0 + n) * ldb + k0 + k];
                Bs[k][n] = v;
            }
        }
        __syncthreads();
        #pragma unroll
        for (int k = 0; k < 16; k++) {
            float4 a = *(const float4*)&As[k][ty * 4];
            float4 b = *(const float4*)&Bs[k][tx * 4];
            float av[4] = {a.x, a.y, a.z, a.w};
            float bv[4] = {b.x, b.y, b.z, b.w};
            #pragma unroll
            for (int i = 0; i < 4; i++)
                #pragma unroll
                for (int j = 0; j < 4; j++)
                    acc[i][j] = fmaf(av[i], bv[j], acc[i][j]);
        }
        __syncthreads();
    }

    #pragma unroll
    for (int i = 0; i < 4; i++) {
        int m = m0 + ty * 4 + i;
        if (m >= M) continue;
        float bsv = bias ? bias[m] : 0.f;
        #pragma unroll
        for (int j = 0; j < 4; j++) {
            int n = n0 + tx * 4 + j;
            if (n >= N) continue;
            float v = acc[i][j] * alpha + bsv;
            if (resid) v += resid[(long long)m * ldres + n];
            Cm[(long long)m * ldc + n] = v;
        }
    }
}

// ---------------- softmax over last dim (one warp per row) --------------------
__global__ void softmax_rows(float* __restrict__ S, int rows, int cols)
{
    int warp = (blockIdx.x * blockDim.x + threadIdx.x) >> 5;
    int lane = threadIdx.x & 31;
    if (warp >= rows) return;
    float* row = S + (long long)warp * cols;
    float mx = -INFINITY;
    for (int i = lane; i < cols; i += 32) mx = fmaxf(mx, row[i]);
    #pragma unroll
    for (int o = 16; o; o >>= 1) mx = fmaxf(mx, __shfl_xor_sync(0xffffffffu, mx, o));
    float sum = 0.f;
    for (int i = lane; i < cols; i += 32) {
        float e = __expf(row[i] - mx);
        row[i] = e;
        sum += e;
    }
    #pragma unroll
    for (int o = 16; o; o >>= 1) sum += __shfl_xor_sync(0xffffffffu, sum, o);
    float inv = 1.f / sum;
    for (int i = lane; i < cols; i += 32) row[i] *= inv;
}

// ---------------- BEV grid transform ------------------------------------------
__global__ void grid_sample_kernel(const float* __restrict__ in, float* __restrict__ out)
{
    int idx = blockIdx.x * blockDim.x + threadIdx.x;
    if (idx >= 512 * 50 * 50) return;
    int i = idx % 50;
    int j = (idx / 50) % 50;
    int c = idx / 2500;
    int iy = __float2int_rn(0.625f * (float)j + 0.1875f);
    int ix = __float2int_rn(0.625f * (float)i + 0.1875f);
    out[idx] = in[c * 1024 + iy * 32 + ix];
}

// ---------------- pixel shuffle r=2 -------------------------------------------
__global__ void pixel_shuffle_kernel(const float* __restrict__ in, float* __restrict__ out)
{
    int idx = blockIdx.x * blockDim.x + threadIdx.x;
    if (idx >= 512 * 100 * 100) return;
    int ox = idx % 100;
    int oy = (idx / 100) % 100;
    int c = idx / 10000;
    int y = oy >> 1, ry = oy & 1;
    int x = ox >> 1, rx = ox & 1;
    out[idx] = in[(c * 4 + ry * 2 + rx) * 2500 + y * 50 + x];
}

// ---------------- final 1x1 conv (512 -> 6) + sigmoid -------------------------
__global__ void conv1x1_sigmoid_kernel(
    const float* __restrict__ in, const float* __restrict__ w,
    const float* __restrict__ b, float* __restrict__ out)
{
    int idx = blockIdx.x * blockDim.x + threadIdx.x;
    if (idx >= 6 * 10000) return;
    int p = idx % 10000;
    int cls = idx / 10000;
    float acc = b[cls];
    const float* wp = w + cls * 512;
    #pragma unroll 4
    for (int c = 0; c < 512; c++)
        acc = fmaf(in[c * 10000 + p], wp[c], acc);
    out[idx] = 1.f / (1.f + __expf(-acc));
}

__global__ void copy_kernel(const float* __restrict__ in, float* __restrict__ out, int n)
{
    int i = blockIdx.x * blockDim.x + threadIdx.x;
    if (i < n) out[i] = in[i];
}

// ---------------- host orchestration -----------------------------------------
static inline dim3 tile_grid(int M, int N, int Z)
{
    return dim3((unsigned)((N + 63) / 64), (unsigned)((M + 63) / 64), (unsigned)Z);
}

static void launch_conv_tc(const float* in, const float* w, float* out, int Co, int H, int W,
                           const float* bias,
                           const float* g, const float* bb, const float* m, const float* v,
                           const float* res, int relu)
{
    int P = H * W;
    dim3 grid((P + 63) / 64, Co / 128);
    conv3x3_mma<<<grid, 256, 49152>>>(in, w, out, Co, H, W, bias, g, bb, m, v, res, relu);
}

extern "C" void kernel_launch(void* const* d_in, const int* in_sizes, int n_in,
                              void* d_out, int out_size)
{
    const float* x       = (const float*)d_in[0];
    const float* qkv_w   = (const float*)d_in[1];
    const float* proj_w  = (const float*)d_in[2];
    const float* proj_b  = (const float*)d_in[3];
    const float* head_w  = (const float*)d_in[4];
    const float* head_b  = (const float*)d_in[5];
    const float* body_w  = (const float*)d_in[6];
    const float* body_b  = (const float*)d_in[7];
    const float* btail_w = (const float*)d_in[8];
    const float* btail_b = (const float*)d_in[9];
    const float* up_w    = (const float*)d_in[10];
    const float* up_b    = (const float*)d_in[11];
    const float* tail_w  = (const float*)d_in[12];
    const float* tail_b  = (const float*)d_in[13];
    const float* c1_w    = (const float*)d_in[14];
    const float* bn1_g   = (const float*)d_in[15];
    const float* bn1_b   = (const float*)d_in[16];
    const float* bn1_m   = (const float*)d_in[17];
    const float* bn1_v   = (const float*)d_in[18];
    const float* c2_w    = (const float*)d_in[19];
    const float* bn2_g   = (const float*)d_in[20];
    const float* bn2_b   = (const float*)d_in[21];
    const float* bn2_m   = (const float*)d_in[22];
    const float* bn2_v   = (const float*)d_in[23];
    const float* c3_w    = (const float*)d_in[24];
    const float* c3_b    = (const float*)d_in[25];

    float *gx, *gqkv, *gS, *gatt, *gh, *b0, *b1, *b2;
    cudaGetSymbolAddress((void**)&gx,   g_x);
    cudaGetSymbolAddress((void**)&gqkv, g_qkv);
    cudaGetSymbolAddress((void**)&gS,   g_S);
    cudaGetSymbolAddress((void**)&gatt, g_att);
    cudaGetSymbolAddress((void**)&gh,   g_h);
    cudaGetSymbolAddress((void**)&b0,   g_b0);
    cudaGetSymbolAddress((void**)&b1,   g_b1);
    cudaGetSymbolAddress((void**)&b2,   g_b2);

    copy_kernel<<<(512 * 1024 + 255) / 256, 256>>>(x, gx, 512 * 1024);

    const float scale = 0.044194173824159216f;  // 512^-0.5

    // ---- 8 self-attention blocks (SIMT) ----
    for (int i = 0; i < 8; i++) {
        gemm_kernel<<<tile_grid(1536, 1024, 1), 256>>>(
            qkv_w + (long long)i * 512 * 1536, 1536, 1, 0,
            gx, 1024, 0, 0,
            gqkv, 1024, 0,
            1536, 1024, 512, 1.f, nullptr, nullptr, 0);

        gemm_kernel<<<tile_grid(1024, 1024, 8), 256>>>(
            gqkv, 1024, 1, 64 * 1024,
            gqkv + 512 * 1024, 1024, 0, 64 * 1024,
            gS, 1024, 1024 * 1024,
            1024, 1024, 64, scale, nullptr, nullptr, 0);

        softmax_rows<<<1024, 256>>>(gS, 8 * 1024, 1024);

        gemm_kernel<<<tile_grid(64, 1024, 8), 256>>>(
            gqkv + 1024 * 1024, 1024, 0, 64 * 1024,
            gS, 1024, 1, 1024 * 1024,
            gatt, 1024, 64 * 1024,
            64, 1024, 1024, 1.f, nullptr, nullptr, 0);

        gemm_kernel<<<tile_grid(512, 1024, 1), 256>>>(
            proj_w + (long long)i * 512 * 512, 512, 1, 0,
            gatt, 1024, 0, 0,
            gx, 1024, 0,
            512, 1024, 512, 1.f, proj_b + i * 512, gx, 1024);
    }

    // ---- BEV grid transform ----
    grid_sample_kernel<<<(512 * 2500 + 255) / 256, 256>>>(gx, b0);

    // ---- EDSR (bf16-split mma.sync convs) ----
    launch_conv_tc(b0, head_w, gh, 512, 50, 50, head_b, 0, 0, 0, 0, nullptr, 0);
    const float* rcur = gh;
    float* bufs[2] = {b1, b2};
    for (int i = 0; i < 8; i++) {
        const float* w0 = body_w + (long long)i * 2 * 512 * CONVK;
        const float* w1 = w0 + (long long)512 * CONVK;
        launch_conv_tc(rcur, w0, b0, 512, 50, 50, body_b + i * 1024, 0, 0, 0, 0, nullptr, 1);
        float* rnext = bufs[i & 1];
        launch_conv_tc(b0, w1, rnext, 512, 50, 50, body_b + i * 1024 + 512, 0, 0, 0, 0, rcur, 0);
        rcur = rnext;
    }
    launch_conv_tc(rcur, btail_w, b1, 512, 50, 50, btail_b, 0, 0, 0, 0, gh, 0);
    launch_conv_tc(b1, up_w, b2, 2048, 50, 50, up_b, 0, 0, 0, 0, nullptr, 0);
    pixel_shuffle_kernel<<<(512 * 10000 + 255) / 256, 256>>>(b2, b0);
    launch_conv_tc(b0, tail_w, b1, 512, 100, 100, tail_b, 0, 0, 0, 0, nullptr, 0);

    // ---- classifier ----
    launch_conv_tc(b1, c1_w, b0, 512, 100, 100, nullptr, bn1_g, bn1_b, bn1_m, bn1_v, nullptr, 1);
    launch_conv_tc(b0, c2_w, b1, 512, 100, 100, nullptr, bn2_g, bn2_b, bn2_m, bn2_v, nullptr, 1);
    conv1x1_sigmoid_kernel<<<(6 * 10000 + 255) / 256, 256>>>(b1, c3_w, c3_b, (float*)d_out);
}

// round 9
// speedup vs baseline: 2.6295x; 1.3985x over previous
#include <cuda_runtime.h>
#include <cuda_bf16.h>
#include <math.h>
#include <stdint.h>

#define CONVK 4608   // 512 * 9
#define LW    2359296  // 512*4608 weight elements per standard layer

// ---------------- scratch buffers (device globals; no allocations allowed) ----
__device__ float g_x[512 * 1024];          // token features (C, N)
__device__ float g_qkv[1536 * 1024];       // qkv (3C, N)
__device__ float g_S[8 * 1024 * 1024];     // attention scores
__device__ float g_att[512 * 1024];        // attention output (C, N)
__device__ float g_h[512 * 2500];          // EDSR head output (skip)
__device__ float g_b0[512 * 10000];
__device__ float g_b1[512 * 10000];
__device__ float g_b2[512 * 10000];        // up-conv output (2048*2500)

// pre-split bf16 planes (persistent)
__device__ unsigned short g_whi[25 * LW];             // all conv weights, hi
__device__ unsigned short g_wlo[25 * LW];             // lo
__device__ unsigned short g_ihi[10048 * CONVK];       // im2col hi  (Ppad x K)
__device__ unsigned short g_ilo[10048 * CONVK];       // im2col lo

// =================== warp-MMA / async helpers =================================
__device__ __forceinline__ uint32_t smem_u32(const void* p) {
    uint32_t a;
    asm("{ .reg .u64 t; cvta.to.shared.u64 t, %1; cvt.u32.u64 %0, t; }" : "=r"(a) : "l"(p));
    return a;
}
__device__ __forceinline__ void ldsm_x4(uint32_t (&r)[4], uint32_t addr) {
    asm volatile("ldmatrix.sync.aligned.m8n8.x4.shared.b16 {%0,%1,%2,%3}, [%4];"
        : "=r"(r[0]), "=r"(r[1]), "=r"(r[2]), "=r"(r[3]) : "r"(addr));
}
__device__ __forceinline__ void mma16816(float* d, const uint32_t (&a)[4], const uint32_t* b) {
    asm volatile("mma.sync.aligned.m16n8k16.row.col.f32.bf16.bf16.f32 "
        "{%0,%1,%2,%3}, {%4,%5,%6,%7}, {%8,%9}, {%0,%1,%2,%3};"
        : "+f"(d[0]), "+f"(d[1]), "+f"(d[2]), "+f"(d[3])
        : "r"(a[0]), "r"(a[1]), "r"(a[2]), "r"(a[3]), "r"(b[0]), "r"(b[1]));
}
__device__ __forceinline__ void cp16(uint32_t dst, const void* src) {
    asm volatile("cp.async.cg.shared.global [%0], [%1], 16;" :: "r"(dst), "l"(src));
}
#define CP_COMMIT() asm volatile("cp.async.commit_group;" ::: "memory")
#define CP_WAIT1()  asm volatile("cp.async.wait_group 1;" ::: "memory")

// =================== split kernels ============================================
__global__ void wsplit_kernel(const float* __restrict__ w,
                              unsigned short* __restrict__ hi,
                              unsigned short* __restrict__ lo, int n)
{
    int i = blockIdx.x * blockDim.x + threadIdx.x;
    if (i >= n) return;
    float v = w[i];
    __nv_bfloat16 h = __float2bfloat16(v);
    __nv_bfloat16 l = __float2bfloat16(v - __bfloat162float(h));
    hi[i] = *reinterpret_cast<unsigned short*>(&h);
    lo[i] = *reinterpret_cast<unsigned short*>(&l);
}

// im2col + split: out (Ppad, 4608) bf16 hi/lo from (512, H, W) fp32
__global__ void im2col_split(const float* __restrict__ in, int H, int W, int P, int Ppad,
                             unsigned short* __restrict__ hi, unsigned short* __restrict__ lo)
{
    long long idx = (long long)blockIdx.x * blockDim.x + threadIdx.x;
    long long total = (long long)Ppad * CONVK;
    if (idx >= total) return;
    int k = (int)(idx % CONVK);
    int p = (int)(idx / CONVK);
    float v = 0.f;
    if (p < P) {
        int ci = k / 9, tap = k - ci * 9;
        int t3 = tap / 3;
        int y = p / W + t3 - 1;
        int x = p - (p / W) * W + (tap - t3 * 3) - 1;
        if ((unsigned)y < (unsigned)H && (unsigned)x < (unsigned)W)
            v = in[(size_t)ci * P + y * W + x];
    }
    __nv_bfloat16 h = __float2bfloat16(v);
    __nv_bfloat16 l = __float2bfloat16(v - __bfloat162float(h));
    hi[idx] = *reinterpret_cast<unsigned short*>(&h);
    lo[idx] = *reinterpret_cast<unsigned short*>(&l);
}

// =================== pipelined bf16-split GEMM (conv) =========================
// C(Co, P) = A(Co, 4608) * B(P, 4608)^T with 3-term hi/lo passes.
// 128x64 tile, K-chunk 64, 2-stage cp.async pipeline, 96KB smem.
__global__ __launch_bounds__(256)
void gemm_conv_mma(const unsigned short* __restrict__ Ahi, const unsigned short* __restrict__ Alo,
                   const unsigned short* __restrict__ Bhi, const unsigned short* __restrict__ Blo,
                   float* __restrict__ out, int Co, int P,
                   const float* __restrict__ bias,
                   const float* __restrict__ bn_g, const float* __restrict__ bn_b,
                   const float* __restrict__ bn_m, const float* __restrict__ bn_v,
                   const float* __restrict__ resid, int relu)
{
    constexpr int K = CONVK;
    constexpr uint32_t STG = 49152;
    constexpr uint32_t AHI = 0, ALO = 16384, BHI = 32768, BLO = 40960;
    extern __shared__ char sm[];
    const uint32_t sbase = smem_u32(sm);

    const int tid = threadIdx.x;
    const int lane = tid & 31;
    const int wid = tid >> 5;
    const int wm = wid >> 1;
    const int wn = wid & 1;
    const int m0 = blockIdx.y * 128;
    const int n0 = blockIdx.x * 64;

    // per-lane ldmatrix address components (verified mapping)
    const uint32_t xorv = (uint32_t)(lane & 7) << 4;
    const uint32_t a_cg = (uint32_t)(lane >> 4) << 4;
    const uint32_t b_cg = (uint32_t)((lane >> 3) & 1) << 4;
    uint32_t arow[2], brow[2];
    #pragma unroll
    for (int mt = 0; mt < 2; mt++)
        arow[mt] = (uint32_t)(wm * 32 + mt * 16 + (lane & 15)) * 128;
    const int b_r = wn * 32 + (lane & 7) + ((lane >> 4) * 8);
    #pragma unroll
    for (int nt = 0; nt < 2; nt++)
        brow[nt] = (uint32_t)(b_r + nt * 16) * 128;

    // staging slot precompute: srow in [0,32), sc16 in [0,8)
    const int srow = tid >> 3;
    const int sc16 = tid & 7;
    const uint32_t soff_base = (uint32_t)(sc16 * 16);

    float acc[2][4][4] = {};

    // ---- stage one K-chunk into buffer SB ----
    // A: 128 rows x 8 segs, 4 rows/thread. B: 64 rows x 8 segs, 2 rows/thread.
    #define STAGE(SB, K0) do {                                                        \
        uint32_t base = sbase + (uint32_t)(SB) * STG;                                 \
        _Pragma("unroll")                                                             \
        for (int s = 0; s < 4; s++) {                                                 \
            int row = srow + s * 32;                                                  \
            uint32_t off = (uint32_t)row * 128 + (soff_base ^ (((uint32_t)row & 7) << 4)); \
            cp16(base + AHI + off, Ahi + (size_t)(m0 + row) * K + (K0) + sc16 * 8);   \
            cp16(base + ALO + off, Alo + (size_t)(m0 + row) * K + (K0) + sc16 * 8);   \
        }                                                                             \
        _Pragma("unroll")                                                             \
        for (int s = 0; s < 2; s++) {                                                 \
            int row = srow + s * 32;                                                  \
            uint32_t off = (uint32_t)row * 128 + (soff_base ^ (((uint32_t)row & 7) << 4)); \
            cp16(base + BHI + off, Bhi + (size_t)(n0 + row) * K + (K0) + sc16 * 8);   \
            cp16(base + BLO + off, Blo + (size_t)(n0 + row) * K + (K0) + sc16 * 8);   \
        }                                                                             \
    } while (0)

    STAGE(0, 0);
    CP_COMMIT();

    #pragma unroll 1
    for (int c = 0; c < 72; c++) {
        if (c < 71) STAGE((c + 1) & 1, (c + 1) * 64);
        CP_COMMIT();
        CP_WAIT1();
        __syncthreads();

        const uint32_t stg = sbase + (uint32_t)(c & 1) * STG;
        #pragma unroll
        for (int pass = 0; pass < 3; pass++) {
            const uint32_t ao = stg + ((pass == 2) ? ALO : AHI);
            const uint32_t bo = stg + ((pass == 1) ? BLO : BHI);
            #pragma unroll
            for (int kk = 0; kk < 4; kk++) {
                const uint32_t cbA = (((uint32_t)kk << 5) | a_cg) ^ xorv;
                const uint32_t cbB = (((uint32_t)kk << 5) | b_cg) ^ xorv;
                uint32_t a0[4], a1[4], b0[4], b1[4];
                ldsm_x4(a0, ao + arow[0] + cbA);
                ldsm_x4(a1, ao + arow[1] + cbA);
                ldsm_x4(b0, bo + brow[0] + cbB);
                ldsm_x4(b1, bo + brow[1] + cbB);
                mma16816(acc[0][0], a0, &b0[0]);
                mma16816(acc[0][1], a0, &b0[2]);
                mma16816(acc[0][2], a0, &b1[0]);
                mma16816(acc[0][3], a0, &b1[2]);
                mma16816(acc[1][0], a1, &b0[0]);
                mma16816(acc[1][1], a1, &b0[2]);
                mma16816(acc[1][2], a1, &b1[0]);
                mma16816(acc[1][3], a1, &b1[2]);
            }
        }
        __syncthreads();
    }

    // ---- epilogue ----
    #pragma unroll
    for (int mt = 0; mt < 2; mt++) {
        #pragma unroll
        for (int nt = 0; nt < 4; nt++) {
            int row = m0 + wm * 32 + mt * 16 + (lane >> 2);
            int col = n0 + wn * 32 + nt * 8 + (lane & 3) * 2;
            if (col >= P) continue;
            #pragma unroll
            for (int half = 0; half < 2; half++) {
                int r = row + half * 8;
                float v0 = acc[mt][nt][half * 2 + 0];
                float v1 = acc[mt][nt][half * 2 + 1];
                if (bias) { v0 += bias[r]; v1 += bias[r]; }
                if (bn_g) {
                    float sc = bn_g[r] * rsqrtf(bn_v[r] + 1e-5f);
                    float sh = bn_b[r] - bn_m[r] * sc;
                    v0 = v0 * sc + sh; v1 = v1 * sc + sh;
                }
                if (resid) {
                    float2 rr = *(const float2*)(resid + (size_t)r * P + col);
                    v0 += rr.x; v1 += rr.y;
                }
                if (relu) { v0 = fmaxf(v0, 0.f); v1 = fmaxf(v1, 0.f); }
                *(float2*)(out + (size_t)r * P + col) = make_float2(v0, v1);
            }
        }
    }
    #undef STAGE
}

// =================== SIMT GEMM (attention path) ===============================
__global__ void gemm_kernel(
    const float* __restrict__ A, int lda, int transA, long long strideA,
    const float* __restrict__ B, int ldb, int transB, long long strideB,
    float* __restrict__ Cm, int ldc, long long strideC,
    int M, int N, int K, float alpha,
    const float* __restrict__ bias,
    const float* __restrict__ resid, int ldres)
{
    int bz = blockIdx.z;
    A += (long long)bz * strideA;
    B += (long long)bz * strideB;
    Cm += (long long)bz * strideC;
    if (resid) resid += (long long)bz * strideC;

    __shared__ float As[16][64];
    __shared__ float Bs[16][64];

    int tid = threadIdx.x;
    int tx = tid & 15, ty = tid >> 4;
    int m0 = blockIdx.y * 64, n0 = blockIdx.x * 64;

    float acc[4][4] = {};

    for (int k0 = 0; k0 < K; k0 += 16) {
        if (!transA) {
            #pragma unroll
            for (int s = 0; s < 4; s++) {
                int idx = tid + s * 256;
                int m = idx >> 4, k = idx & 15;
                float v = 0.f;
                if (m0 + m < M && k0 + k < K) v = A[(long long)(m0 + m) * lda + k0 + k];
                As[k][m] = v;
            }
        } else {
            #pragma unroll
            for (int s = 0; s < 4; s++) {
                int idx = tid + s * 256;
                int m = idx & 63, k = idx >> 6;
                float v = 0.f;
                if (m0 + m < M && k0 + k < K) v = A[(long long)(k0 + k) * lda + m0 + m];
                As[k][m] = v;
            }
        }
        if (!transB) {
            #pragma unroll
            for (int s = 0; s < 4; s++) {
                int idx = tid + s * 256;
                int n = idx & 63, k = idx >> 6;
                float v = 0.f;
                if (n0 + n < N && k0 + k < K) v = B[(long long)(k0 + k) * ldb + n0 + n];
                Bs[k][n] = v;
            }
        } else {
            #pragma unroll
            for (int s = 0; s < 4; s++) {
                int idx = tid + s * 256;
                int k = idx & 15, n = idx >> 4;
                float v = 0.f;
                if (n0 + n < N && k0 + k < K) v = B[(long long)(n0 + n) * ldb + k0 + k];
                Bs[k][n] = v;
            }
        }
        __syncthreads();
        #pragma unroll
        for (int k = 0; k < 16; k++) {
            float4 a = *(const float4*)&As[k][ty * 4];
            float4 b = *(const float4*)&Bs[k][tx * 4];
            float av[4] = {a.x, a.y, a.z, a.w};
            float bv[4] = {b.x, b.y, b.z, b.w};
            #pragma unroll
            for (int i = 0; i < 4; i++)
                #pragma unroll
                for (int j = 0; j < 4; j++)
                    acc[i][j] = fmaf(av[i], bv[j], acc[i][j]);
        }
        __syncthreads();
    }

    #pragma unroll
    for (int i = 0; i < 4; i++) {
        int m = m0 + ty * 4 + i;
        if (m >= M) continue;
        float bsv = bias ? bias[m] : 0.f;
        #pragma unroll
        for (int j = 0; j < 4; j++) {
            int n = n0 + tx * 4 + j;
            if (n >= N) continue;
            float v = acc[i][j] * alpha + bsv;
            if (resid) v += resid[(long long)m * ldres + n];
            Cm[(long long)m * ldc + n] = v;
        }
    }
}

// ---------------- softmax over last dim (one warp per row) --------------------
__global__ void softmax_rows(float* __restrict__ S, int rows, int cols)
{
    int warp = (blockIdx.x * blockDim.x + threadIdx.x) >> 5;
    int lane = threadIdx.x & 31;
    if (warp >= rows) return;
    float* row = S + (long long)warp * cols;
    float mx = -INFINITY;
    for (int i = lane; i < cols; i += 32) mx = fmaxf(mx, row[i]);
    #pragma unroll
    for (int o = 16; o; o >>= 1) mx = fmaxf(mx, __shfl_xor_sync(0xffffffffu, mx, o));
    float sum = 0.f;
    for (int i = lane; i < cols; i += 32) {
        float e = __expf(row[i] - mx);
        row[i] = e;
        sum += e;
    }
    #pragma unroll
    for (int o = 16; o; o >>= 1) sum += __shfl_xor_sync(0xffffffffu, sum, o);
    float inv = 1.f / sum;
    for (int i = lane; i < cols; i += 32) row[i] *= inv;
}

// ---------------- BEV grid transform ------------------------------------------
__global__ void grid_sample_kernel(const float* __restrict__ in, float* __restrict__ out)
{
    int idx = blockIdx.x * blockDim.x + threadIdx.x;
    if (idx >= 512 * 50 * 50) return;
    int i = idx % 50;
    int j = (idx / 50) % 50;
    int c = idx / 2500;
    int iy = __float2int_rn(0.625f * (float)j + 0.1875f);
    int ix = __float2int_rn(0.625f * (float)i + 0.1875f);
    out[idx] = in[c * 1024 + iy * 32 + ix];
}

// ---------------- pixel shuffle r=2 -------------------------------------------
__global__ void pixel_shuffle_kernel(const float* __restrict__ in, float* __restrict__ out)
{
    int idx = blockIdx.x * blockDim.x + threadIdx.x;
    if (idx >= 512 * 100 * 100) return;
    int ox = idx % 100;
    int oy = (idx / 100) % 100;
    int c = idx / 10000;
    int y = oy >> 1, ry = oy & 1;
    int x = ox >> 1, rx = ox & 1;
    out[idx] = in[(c * 4 + ry * 2 + rx) * 2500 + y * 50 + x];
}

// ---------------- final 1x1 conv (512 -> 6) + sigmoid -------------------------
__global__ void conv1x1_sigmoid_kernel(
    const float* __restrict__ in, const float* __restrict__ w,
    const float* __restrict__ b, float* __restrict__ out)
{
    int idx = blockIdx.x * blockDim.x + threadIdx.x;
    if (idx >= 6 * 10000) return;
    int p = idx % 10000;
    int cls = idx / 10000;
    float acc = b[cls];
    const float* wp = w + cls * 512;
    #pragma unroll 4
    for (int c = 0; c < 512; c++)
        acc = fmaf(in[c * 10000 + p], wp[c], acc);
    out[idx] = 1.f / (1.f + __expf(-acc));
}

__global__ void copy_kernel(const float* __restrict__ in, float* __restrict__ out, int n)
{
    int i = blockIdx.x * blockDim.x + threadIdx.x;
    if (i < n) out[i] = in[i];
}

// ---------------- host orchestration -----------------------------------------
static inline dim3 tile_grid(int M, int N, int Z)
{
    return dim3((unsigned)((N + 63) / 64), (unsigned)((M + 63) / 64), (unsigned)Z);
}

struct ConvCtx {
    unsigned short *whi, *wlo, *ihi, *ilo;
};

static void conv_tc(const ConvCtx& cx, const float* in, long long woff, float* out,
                    int Co, int H, int W,
                    const float* bias,
                    const float* g, const float* bb, const float* m, const float* v,
                    const float* res, int relu)
{
    int P = H * W;
    int Ppad = ((P + 63) / 64) * 64;
    long long tot = (long long)Ppad * CONVK;
    im2col_split<<<(unsigned)((tot + 255) / 256), 256>>>(in, H, W, P, Ppad, cx.ihi, cx.ilo);
    dim3 grid((unsigned)(Ppad / 64), (unsigned)(Co / 128));
    gemm_conv_mma<<<grid, 256, 98304>>>(cx.whi + woff, cx.wlo + woff, cx.ihi, cx.ilo,
                                        out, Co, P, bias, g, bb, m, v, res, relu);
}

extern "C" void kernel_launch(void* const* d_in, const int* in_sizes, int n_in,
                              void* d_out, int out_size)
{
    const float* x       = (const float*)d_in[0];
    const float* qkv_w   = (const float*)d_in[1];
    const float* proj_w  = (const float*)d_in[2];
    const float* proj_b  = (const float*)d_in[3];
    const float* head_w  = (const float*)d_in[4];
    const float* head_b  = (const float*)d_in[5];
    const float* body_w  = (const float*)d_in[6];
    const float* body_b  = (const float*)d_in[7];
    const float* btail_w = (const float*)d_in[8];
    const float* btail_b = (const float*)d_in[9];
    const float* up_w    = (const float*)d_in[10];
    const float* up_b    = (const float*)d_in[11];
    const float* tail_w  = (const float*)d_in[12];
    const float* tail_b  = (const float*)d_in[13];
    const float* c1_w    = (const float*)d_in[14];
    const float* bn1_g   = (const float*)d_in[15];
    const float* bn1_b   = (const float*)d_in[16];
    const float* bn1_m   = (const float*)d_in[17];
    const float* bn1_v   = (const float*)d_in[18];
    const float* c2_w    = (const float*)d_in[19];
    const float* bn2_g   = (const float*)d_in[20];
    const float* bn2_b   = (const float*)d_in[21];
    const float* bn2_m   = (const float*)d_in[22];
    const float* bn2_v   = (const float*)d_in[23];
    const float* c3_w    = (const float*)d_in[24];
    const float* c3_b    = (const float*)d_in[25];

    float *gx, *gqkv, *gS, *gatt, *gh, *b0, *b1, *b2;
    cudaGetSymbolAddress((void**)&gx,   g_x);
    cudaGetSymbolAddress((void**)&gqkv, g_qkv);
    cudaGetSymbolAddress((void**)&gS,   g_S);
    cudaGetSymbolAddress((void**)&gatt, g_att);
    cudaGetSymbolAddress((void**)&gh,   g_h);
    cudaGetSymbolAddress((void**)&b0,   g_b0);
    cudaGetSymbolAddress((void**)&b1,   g_b1);
    cudaGetSymbolAddress((void**)&b2,   g_b2);

    ConvCtx cx;
    cudaGetSymbolAddress((void**)&cx.whi, g_whi);
    cudaGetSymbolAddress((void**)&cx.wlo, g_wlo);
    cudaGetSymbolAddress((void**)&cx.ihi, g_ihi);
    cudaGetSymbolAddress((void**)&cx.ilo, g_ilo);

    cudaFuncSetAttribute(gemm_conv_mma, cudaFuncAttributeMaxDynamicSharedMemorySize, 98304);

    // ---- weight pre-split (every call; deterministic) ----
    {
        auto ws = [&](const float* src, long long off, int n) {
            wsplit_kernel<<<(unsigned)((n + 255) / 256), 256>>>(src, cx.whi + off, cx.wlo + off, n);
        };
        ws(head_w,  0,          LW);
        ws(body_w,  (long long)1 * LW,  16 * LW);
        ws(btail_w, (long long)17 * LW, LW);
        ws(up_w,    (long long)18 * LW, 4 * LW);
        ws(tail_w,  (long long)22 * LW, LW);
        ws(c1_w,    (long long)23 * LW, LW);
        ws(c2_w,    (long long)24 * LW, LW);
    }

    copy_kernel<<<(512 * 1024 + 255) / 256, 256>>>(x, gx, 512 * 1024);

    const float scale = 0.044194173824159216f;  // 512^-0.5

    // ---- 8 self-attention blocks (SIMT) ----
    for (int i = 0; i < 8; i++) {
        gemm_kernel<<<tile_grid(1536, 1024, 1), 256>>>(
            qkv_w + (long long)i * 512 * 1536, 1536, 1, 0,
            gx, 1024, 0, 0,
            gqkv, 1024, 0,
            1536, 1024, 512, 1.f, nullptr, nullptr, 0);

        gemm_kernel<<<tile_grid(1024, 1024, 8), 256>>>(
            gqkv, 1024, 1, 64 * 1024,
            gqkv + 512 * 1024, 1024, 0, 64 * 1024,
            gS, 1024, 1024 * 1024,
            1024, 1024, 64, scale, nullptr, nullptr, 0);

        softmax_rows<<<1024, 256>>>(gS, 8 * 1024, 1024);

        gemm_kernel<<<tile_grid(64, 1024, 8), 256>>>(
            gqkv + 1024 * 1024, 1024, 0, 64 * 1024,
            gS, 1024, 1, 1024 * 1024,
            gatt, 1024, 64 * 1024,
            64, 1024, 1024, 1.f, nullptr, nullptr, 0);

        gemm_kernel<<<tile_grid(512, 1024, 1), 256>>>(
            proj_w + (long long)i * 512 * 512, 512, 1, 0,
            gatt, 1024, 0, 0,
            gx, 1024, 0,
            512, 1024, 512, 1.f, proj_b + i * 512, gx, 1024);
    }

    // ---- BEV grid transform ----
    grid_sample_kernel<<<(512 * 2500 + 255) / 256, 256>>>(gx, b0);

    // ---- EDSR (pipelined bf16-split GEMM convs) ----
    conv_tc(cx, b0, 0, gh, 512, 50, 50, head_b, 0, 0, 0, 0, nullptr, 0);
    const float* rcur = gh;
    float* bufs[2] = {b1, b2};
    for (int i = 0; i < 8; i++) {
        long long w0 = (long long)(1 + 2 * i) * LW;
        long long w1 = (long long)(2 + 2 * i) * LW;
        conv_tc(cx, rcur, w0, b0, 512, 50, 50, body_b + i * 1024, 0, 0, 0, 0, nullptr, 1);
        float* rnext = bufs[i & 1];
        conv_tc(cx, b0, w1, rnext, 512, 50, 50, body_b + i * 1024 + 512, 0, 0, 0, 0, rcur, 0);
        rcur = rnext;
    }
    conv_tc(cx, rcur, (long long)17 * LW, b1, 512, 50, 50, btail_b, 0, 0, 0, 0, gh, 0);
    conv_tc(cx, b1, (long long)18 * LW, b2, 2048, 50, 50, up_b, 0, 0, 0, 0, nullptr, 0);
    pixel_shuffle_kernel<<<(512 * 10000 + 255) / 256, 256>>>(b2, b0);
    conv_tc(cx, b0, (long long)22 * LW, b1, 512, 100, 100, tail_b, 0, 0, 0, 0, nullptr, 0);

    // ---- classifier ----
    conv_tc(cx, b1, (long long)23 * LW, b0, 512, 100, 100, nullptr, bn1_g, bn1_b, bn1_m, bn1_v, nullptr, 1);
    conv_tc(cx, b0, (long long)24 * LW, b1, 512, 100, 100, nullptr, bn2_g, bn2_b, bn2_m, bn2_v, nullptr, 1);
    conv1x1_sigmoid_kernel<<<(6 * 10000 + 255) / 256, 256>>>(b1, c3_w, c3_b, (float*)d_out);
}

// round 13
// speedup vs baseline: 3.5535x; 1.3514x over previous
#include <cuda_runtime.h>
#include <cuda_bf16.h>
#include <math.h>
#include <stdint.h>

#define CONVK 4608     // 512 * 9
#define LW    2359296  // 512*4608 weight elements per standard conv layer

// ---------------- scratch buffers (device globals; no allocations allowed) ----
__device__ float g_x[512 * 1024];          // token features (C, N)
__device__ float g_qkv[1536 * 1024];       // qkv (3C, N)
__device__ float g_S[8 * 1024 * 1024];     // attention scores scratch (fp32)
__device__ float g_att[1024 * 512];        // att^T (N, C) fp32
__device__ float g_h[512 * 2500];          // EDSR head output (skip)
__device__ float g_b0[512 * 10000];
__device__ float g_b1[512 * 10000];
__device__ float g_b2[512 * 10000];        // up-conv output (2048*2500)

// conv pre-split bf16 planes
__device__ unsigned short g_whi[25 * LW];
__device__ unsigned short g_wlo[25 * LW];
__device__ unsigned short g_ihi[10048 * CONVK];
__device__ unsigned short g_ilo[10048 * CONVK];

// attention split planes
__device__ unsigned short g_awh[8 * 1536 * 512], g_awl[8 * 1536 * 512];  // qkv_w^T
__device__ unsigned short g_pwh[8 * 512 * 512],  g_pwl[8 * 512 * 512];   // proj_w^T
__device__ unsigned short g_xth[1024 * 512],     g_xtl[1024 * 512];      // x^T
__device__ unsigned short g_qth[1024 * 512],     g_qtl[1024 * 512];      // q^T
__device__ unsigned short g_kth[1024 * 512],     g_ktl[1024 * 512];      // k^T
__device__ unsigned short g_sh[8 * 1024 * 1024], g_sl[8 * 1024 * 1024];  // softmax(P)
__device__ unsigned short g_vh[512 * 1024],      g_vl[512 * 1024];       // v
__device__ unsigned short g_ath[1024 * 512],     g_atl[1024 * 512];      // att^T

// =================== warp-MMA / async helpers =================================
__device__ __forceinline__ uint32_t smem_u32(const void* p) {
    uint32_t a;
    asm("{ .reg .u64 t; cvta.to.shared.u64 t, %1; cvt.u32.u64 %0, t; }" : "=r"(a) : "l"(p));
    return a;
}
__device__ __forceinline__ void ldsm_x4(uint32_t (&r)[4], uint32_t addr) {
    asm volatile("ldmatrix.sync.aligned.m8n8.x4.shared.b16 {%0,%1,%2,%3}, [%4];"
        : "=r"(r[0]), "=r"(r[1]), "=r"(r[2]), "=r"(r[3]) : "r"(addr));
}
__device__ __forceinline__ void mma16816(float* d, const uint32_t (&a)[4], const uint32_t* b) {
    asm volatile("mma.sync.aligned.m16n8k16.row.col.f32.bf16.bf16.f32 "
        "{%0,%1,%2,%3}, {%4,%5,%6,%7}, {%8,%9}, {%0,%1,%2,%3};"
        : "+f"(d[0]), "+f"(d[1]), "+f"(d[2]), "+f"(d[3])
        : "r"(a[0]), "r"(a[1]), "r"(a[2]), "r"(a[3]), "r"(b[0]), "r"(b[1]));
}
__device__ __forceinline__ void cp16(uint32_t dst, const void* src) {
    asm volatile("cp.async.cg.shared.global [%0], [%1], 16;" :: "r"(dst), "l"(src));
}
#define CP_COMMIT() asm volatile("cp.async.commit_group;" ::: "memory")
#define CP_WAIT1()  asm volatile("cp.async.wait_group 1;" ::: "memory")

__device__ __forceinline__ void split_store(float v, unsigned short* hi, unsigned short* lo,
                                            size_t idx) {
    __nv_bfloat16 h = __float2bfloat16(v);
    __nv_bfloat16 l = __float2bfloat16(v - __bfloat162float(h));
    hi[idx] = *reinterpret_cast<unsigned short*>(&h);
    lo[idx] = *reinterpret_cast<unsigned short*>(&l);
}

// =================== split / transpose-split kernels ==========================
__global__ void wsplit_kernel(const float* __restrict__ w,
                              unsigned short* __restrict__ hi,
                              unsigned short* __restrict__ lo, int n)
{
    int i = blockIdx.x * blockDim.x + threadIdx.x;
    if (i >= n) return;
    split_store(w[i], hi, lo, i);
}

// in (R,C) row-major fp32 -> out (C,R) split bf16
__global__ void tsplit_kernel(const float* __restrict__ in, int R, int C,
                              unsigned short* __restrict__ hi, unsigned short* __restrict__ lo)
{
    __shared__ float t[32][33];
    int c0 = blockIdx.x * 32, r0 = blockIdx.y * 32;
    int tx = threadIdx.x, ty = threadIdx.y;   // block (32, 8)
    #pragma unroll
    for (int s = 0; s < 32; s += 8) {
        int r = r0 + ty + s, cc = c0 + tx;
        t[ty + s][tx] = (r < R && cc < C) ? in[(size_t)r * C + cc] : 0.f;
    }
    __syncthreads();
    #pragma unroll
    for (int s = 0; s < 32; s += 8) {
        int orow = c0 + ty + s;   // index in C
        int ocol = r0 + tx;       // index in R
        if (orow < C && ocol < R)
            split_store(t[tx][ty + s], hi, lo, (size_t)orow * R + ocol);
    }
}

// im2col + split: out (Ppad, 4608) bf16 hi/lo from (512, H, W) fp32
__global__ void im2col_split(const float* __restrict__ in, int H, int W, int P, int Ppad,
                             unsigned short* __restrict__ hi, unsigned short* __restrict__ lo)
{
    long long idx = (long long)blockIdx.x * blockDim.x + threadIdx.x;
    long long total = (long long)Ppad * CONVK;
    if (idx >= total) return;
    int k = (int)(idx % CONVK);
    int p = (int)(idx / CONVK);
    float v = 0.f;
    if (p < P) {
        int ci = k / 9, tap = k - ci * 9;
        int t3 = tap / 3;
        int y = p / W + t3 - 1;
        int x = p - (p / W) * W + (tap - t3 * 3) - 1;
        if ((unsigned)y < (unsigned)H && (unsigned)x < (unsigned)W)
            v = in[(size_t)ci * P + y * W + x];
    }
    split_store(v, hi, lo, (size_t)idx);
}

// =================== generalized pipelined bf16-split GEMM ====================
// C(M, Ncols) = alpha * A(M,K;lda) * B(N,K;ldb)^T  (+bias +BN +resid, relu)
// per-z batch: A += z*sA, B += z*sB, C += z*sC + z*coffC.
// 128x64 tile, K-chunk 64, 2-stage cp.async pipeline, 96KB smem.
// Fragment-reuse inner loop: 8 LDSM + 24 MMA per k16 step (3 split passes).
__global__ __launch_bounds__(256, 2)
void gemm_bf16s(const unsigned short* __restrict__ Ahi_, const unsigned short* __restrict__ Alo_,
                int lda, long long sA,
                const unsigned short* __restrict__ Bhi_, const unsigned short* __restrict__ Blo_,
                int ldb, long long sB,
                float* __restrict__ out, int ldc, long long sC, int coffC,
                int Ncols, int K, float alpha,
                const float* __restrict__ bias,
                const float* __restrict__ bn_g, const float* __restrict__ bn_b,
                const float* __restrict__ bn_m, const float* __restrict__ bn_v,
                const float* __restrict__ resid, int ldres, int relu)
{
    constexpr uint32_t STG = 49152;
    constexpr uint32_t AHI = 0, ALO = 16384, BHI = 32768, BLO = 40960;
    extern __shared__ char sm[];
    const uint32_t sbase = smem_u32(sm);

    const int z = blockIdx.z;
    const unsigned short* Ahi = Ahi_ + (long long)z * sA;
    const unsigned short* Alo = Alo_ + (long long)z * sA;
    const unsigned short* Bhi = Bhi_ + (long long)z * sB;
    const unsigned short* Blo = Blo_ + (long long)z * sB;
    out += (long long)z * sC + (long long)z * coffC;

    const int tid = threadIdx.x;
    const int lane = tid & 31;
    const int wid = tid >> 5;
    const int wm = wid >> 1;
    const int wn = wid & 1;
    const int m0 = blockIdx.y * 128;
    const int n0 = blockIdx.x * 64;
    const int chunks = K >> 6;

    // ldmatrix address components (verified mapping)
    const uint32_t xorv = (uint32_t)(lane & 7) << 4;
    const uint32_t a_cg = (uint32_t)(lane >> 4) << 4;
    const uint32_t b_cg = (uint32_t)((lane >> 3) & 1) << 4;
    uint32_t arow[2], brow[2];
    #pragma unroll
    for (int mt = 0; mt < 2; mt++)
        arow[mt] = (uint32_t)(wm * 32 + mt * 16 + (lane & 15)) * 128;
    const int b_r = wn * 32 + (lane & 7) + ((lane >> 4) * 8);
    #pragma unroll
    for (int nt = 0; nt < 2; nt++)
        brow[nt] = (uint32_t)(b_r + nt * 16) * 128;

    // staging slots: srow in [0,32), sc16 in [0,8)
    const int srow = tid >> 3;
    const int sc16 = tid & 7;
    const uint32_t soff_base = (uint32_t)(sc16 * 16);

    float acc[2][4][4] = {};

    #define STAGE(SB, K0) do {                                                        \
        uint32_t base = sbase + (uint32_t)(SB) * STG;                                 \
        _Pragma("unroll")                                                             \
        for (int s = 0; s < 4; s++) {                                                 \
            int row = srow + s * 32;                                                  \
            uint32_t off = (uint32_t)row * 128 + (soff_base ^ (((uint32_t)row & 7) << 4)); \
            cp16(base + AHI + off, Ahi + (size_t)(m0 + row) * lda + (K0) + sc16 * 8); \
            cp16(base + ALO + off, Alo + (size_t)(m0 + row) * lda + (K0) + sc16 * 8); \
        }                                                                             \
        _Pragma("unroll")                                                             \
        for (int s = 0; s < 2; s++) {                                                 \
            int row = srow + s * 32;                                                  \
            uint32_t off = (uint32_t)row * 128 + (soff_base ^ (((uint32_t)row & 7) << 4)); \
            cp16(base + BHI + off, Bhi + (size_t)(n0 + row) * ldb + (K0) + sc16 * 8); \
            cp16(base + BLO + off, Blo + (size_t)(n0 + row) * ldb + (K0) + sc16 * 8); \
        }                                                                             \
    } while (0)

    STAGE(0, 0);
    CP_COMMIT();

    #pragma unroll 1
    for (int c = 0; c < chunks; c++) {
        if (c < chunks - 1) STAGE((c + 1) & 1, (c + 1) * 64);
        CP_COMMIT();
        CP_WAIT1();
        __syncthreads();

        const uint32_t stg = sbase + (uint32_t)(c & 1) * STG;
        #pragma unroll
        for (int kk = 0; kk < 4; kk++) {
            const uint32_t cbA = (((uint32_t)kk << 5) | a_cg) ^ xorv;
            const uint32_t cbB = (((uint32_t)kk << 5) | b_cg) ^ xorv;
            uint32_t ah0[4], ah1[4], al0[4], al1[4];
            uint32_t bh0[4], bh1[4], bl0[4], bl1[4];
            ldsm_x4(ah0, stg + AHI + arow[0] + cbA);
            ldsm_x4(ah1, stg + AHI + arow[1] + cbA);
            ldsm_x4(bh0, stg + BHI + brow[0] + cbB);
            ldsm_x4(bh1, stg + BHI + brow[1] + cbB);
            ldsm_x4(al0, stg + ALO + arow[0] + cbA);
            ldsm_x4(al1, stg + ALO + arow[1] + cbA);
            ldsm_x4(bl0, stg + BLO + brow[0] + cbB);
            ldsm_x4(bl1, stg + BLO + brow[1] + cbB);
            // pass hi*hi
            mma16816(acc[0][0], ah0, &bh0[0]);
            mma16816(acc[0][1], ah0, &bh0[2]);
            mma16816(acc[0][2], ah0, &bh1[0]);
            mma16816(acc[0][3], ah0, &bh1[2]);
            mma16816(acc[1][0], ah1, &bh0[0]);
            mma16816(acc[1][1], ah1, &bh0[2]);
            mma16816(acc[1][2], ah1, &bh1[0]);
            mma16816(acc[1][3], ah1, &bh1[2]);
            // pass hi*lo
            mma16816(acc[0][0], ah0, &bl0[0]);
            mma16816(acc[0][1], ah0, &bl0[2]);
            mma16816(acc[0][2], ah0, &bl1[0]);
            mma16816(acc[0][3], ah0, &bl1[2]);
            mma16816(acc[1][0], ah1, &bl0[0]);
            mma16816(acc[1][1], ah1, &bl0[2]);
            mma16816(acc[1][2], ah1, &bl1[0]);
            mma16816(acc[1][3], ah1, &bl1[2]);
            // pass lo*hi
            mma16816(acc[0][0], al0, &bh0[0]);
            mma16816(acc[0][1], al0, &bh0[2]);
            mma16816(acc[0][2], al0, &bh1[0]);
            mma16816(acc[0][3], al0, &bh1[2]);
            mma16816(acc[1][0], al1, &bh0[0]);
            mma16816(acc[1][1], al1, &bh0[2]);
            mma16816(acc[1][2], al1, &bh1[0]);
            mma16816(acc[1][3], al1, &bh1[2]);
        }
        __syncthreads();
    }

    // ---- epilogue ----
    #pragma unroll
    for (int mt = 0; mt < 2; mt++) {
        #pragma unroll
        for (int nt = 0; nt < 4; nt++) {
            int row = m0 + wm * 32 + mt * 16 + (lane >> 2);
            int col = n0 + wn * 32 + nt * 8 + (lane & 3) * 2;
            if (col >= Ncols) continue;
            #pragma unroll
            for (int half = 0; half < 2; half++) {
                int r = row + half * 8;
                float v0 = acc[mt][nt][half * 2 + 0] * alpha;
                float v1 = acc[mt][nt][half * 2 + 1] * alpha;
                if (bias) { v0 += bias[r]; v1 += bias[r]; }
                if (bn_g) {
                    float sc = bn_g[r] * rsqrtf(bn_v[r] + 1e-5f);
                    float sh = bn_b[r] - bn_m[r] * sc;
                    v0 = v0 * sc + sh; v1 = v1 * sc + sh;
                }
                if (resid) {
                    float2 rr = *(const float2*)(resid + (size_t)r * ldres + col);
                    v0 += rr.x; v1 += rr.y;
                }
                if (relu) { v0 = fmaxf(v0, 0.f); v1 = fmaxf(v1, 0.f); }
                *(float2*)(out + (size_t)r * ldc + col) = make_float2(v0, v1);
            }
        }
    }
    #undef STAGE
}

// ---------------- softmax (one warp per row) -> split bf16 output -------------
__global__ void softmax_split(float* __restrict__ S,
                              unsigned short* __restrict__ hi, unsigned short* __restrict__ lo,
                              int rows, int cols)
{
    int warp = (blockIdx.x * blockDim.x + threadIdx.x) >> 5;
    int lane = threadIdx.x & 31;
    if (warp >= rows) return;
    float* row = S + (long long)warp * cols;
    unsigned short* ho = hi + (long long)warp * cols;
    unsigned short* lo_ = lo + (long long)warp * cols;
    float mx = -INFINITY;
    for (int i = lane; i < cols; i += 32) mx = fmaxf(mx, row[i]);
    #pragma unroll
    for (int o = 16; o; o >>= 1) mx = fmaxf(mx, __shfl_xor_sync(0xffffffffu, mx, o));
    float sum = 0.f;
    for (int i = lane; i < cols; i += 32) {
        float e = __expf(row[i] - mx);
        row[i] = e;
        sum += e;
    }
    #pragma unroll
    for (int o = 16; o; o >>= 1) sum += __shfl_xor_sync(0xffffffffu, sum, o);
    float inv = 1.f / sum;
    for (int i = lane; i < cols; i += 32) {
        float v = row[i] * inv;
        __nv_bfloat16 h = __float2bfloat16(v);
        __nv_bfloat16 l = __float2bfloat16(v - __bfloat162float(h));
        ho[i] = *reinterpret_cast<unsigned short*>(&h);
        lo_[i] = *reinterpret_cast<unsigned short*>(&l);
    }
}

// ---------------- BEV grid transform ------------------------------------------
__global__ void grid_sample_kernel(const float* __restrict__ in, float* __restrict__ out)
{
    int idx = blockIdx.x * blockDim.x + threadIdx.x;
    if (idx >= 512 * 50 * 50) return;
    int i = idx % 50;
    int j = (idx / 50) % 50;
    int c = idx / 2500;
    int iy = __float2int_rn(0.625f * (float)j + 0.1875f);
    int ix = __float2int_rn(0.625f * (float)i + 0.1875f);
    out[idx] = in[c * 1024 + iy * 32 + ix];
}

// ---------------- pixel shuffle r=2 -------------------------------------------
__global__ void pixel_shuffle_kernel(const float* __restrict__ in, float* __restrict__ out)
{
    int idx = blockIdx.x * blockDim.x + threadIdx.x;
    if (idx >= 512 * 100 * 100) return;
    int ox = idx % 100;
    int oy = (idx / 100) % 100;
    int c = idx / 10000;
    int y = oy >> 1, ry = oy & 1;
    int x = ox >> 1, rx = ox & 1;
    out[idx] = in[(c * 4 + ry * 2 + rx) * 2500 + y * 50 + x];
}

// ---------------- final 1x1 conv (512 -> 6) + sigmoid -------------------------
__global__ void conv1x1_sigmoid_kernel(
    const float* __restrict__ in, const float* __restrict__ w,
    const float* __restrict__ b, float* __restrict__ out)
{
    int idx = blockIdx.x * blockDim.x + threadIdx.x;
    if (idx >= 6 * 10000) return;
    int p = idx % 10000;
    int cls = idx / 10000;
    float acc = b[cls];
    const float* wp = w + cls * 512;
    #pragma unroll 4
    for (int c = 0; c < 512; c++)
        acc = fmaf(in[c * 10000 + p], wp[c], acc);
    out[idx] = 1.f / (1.f + __expf(-acc));
}

__global__ void copy_kernel(const float* __restrict__ in, float* __restrict__ out, int n)
{
    int i = blockIdx.x * blockDim.x + threadIdx.x;
    if (i < n) out[i] = in[i];
}

// ---------------- host orchestration -----------------------------------------
struct ConvCtx {
    unsigned short *whi, *wlo, *ihi, *ilo;
};

static void conv_tc(const ConvCtx& cx, const float* in, long long woff, float* out,
                    int Co, int H, int W,
                    const float* bias,
                    const float* g, const float* bb, const float* m, const float* v,
                    const float* res, int relu)
{
    int P = H * W;
    int Ppad = ((P + 63) / 64) * 64;
    long long tot = (long long)Ppad * CONVK;
    im2col_split<<<(unsigned)((tot + 255) / 256), 256>>>(in, H, W, P, Ppad, cx.ihi, cx.ilo);
    dim3 grid((unsigned)(Ppad / 64), (unsigned)(Co / 128));
    gemm_bf16s<<<grid, 256, 98304>>>(cx.whi + woff, cx.wlo + woff, CONVK, 0,
                                     cx.ihi, cx.ilo, CONVK, 0,
                                     out, P, 0, 0, P, CONVK, 1.f,
                                     bias, g, bb, m, v, res, P, relu);
}

extern "C" void kernel_launch(void* const* d_in, const int* in_sizes, int n_in,
                              void* d_out, int out_size)
{
    const float* x       = (const float*)d_in[0];
    const float* qkv_w   = (const float*)d_in[1];
    const float* proj_w  = (const float*)d_in[2];
    const float* proj_b  = (const float*)d_in[3];
    const float* head_w  = (const float*)d_in[4];
    const float* head_b  = (const float*)d_in[5];
    const float* body_w  = (const float*)d_in[6];
    const float* body_b  = (const float*)d_in[7];
    const float* btail_w = (const float*)d_in[8];
    const float* btail_b = (const float*)d_in[9];
    const float* up_w    = (const float*)d_in[10];
    const float* up_b    = (const float*)d_in[11];
    const float* tail_w  = (const float*)d_in[12];
    const float* tail_b  = (const float*)d_in[13];
    const float* c1_w    = (const float*)d_in[14];
    const float* bn1_g   = (const float*)d_in[15];
    const float* bn1_b   = (const float*)d_in[16];
    const float* bn1_m   = (const float*)d_in[17];
    const float* bn1_v   = (const float*)d_in[18];
    const float* c2_w    = (const float*)d_in[19];
    const float* bn2_g   = (const float*)d_in[20];
    const float* bn2_b   = (const float*)d_in[21];
    const float* bn2_m   = (const float*)d_in[22];
    const float* bn2_v   = (const float*)d_in[23];
    const float* c3_w    = (const float*)d_in[24];
    const float* c3_b    = (const float*)d_in[25];

    float *gx, *gqkv, *gS, *gatt, *gh, *b0, *b1, *b2;
    cudaGetSymbolAddress((void**)&gx,   g_x);
    cudaGetSymbolAddress((void**)&gqkv, g_qkv);
    cudaGetSymbolAddress((void**)&gS,   g_S);
    cudaGetSymbolAddress((void**)&gatt, g_att);
    cudaGetSymbolAddress((void**)&gh,   g_h);
    cudaGetSymbolAddress((void**)&b0,   g_b0);
    cudaGetSymbolAddress((void**)&b1,   g_b1);
    cudaGetSymbolAddress((void**)&b2,   g_b2);

    ConvCtx cx;
    cudaGetSymbolAddress((void**)&cx.whi, g_whi);
    cudaGetSymbolAddress((void**)&cx.wlo, g_wlo);
    cudaGetSymbolAddress((void**)&cx.ihi, g_ihi);
    cudaGetSymbolAddress((void**)&cx.ilo, g_ilo);

    unsigned short *awh, *awl, *pwh, *pwl, *xth, *xtl, *qth, *qtl, *kth, *ktl;
    unsigned short *sh, *sl, *vh, *vl, *ath, *atl;
    cudaGetSymbolAddress((void**)&awh, g_awh);
    cudaGetSymbolAddress((void**)&awl, g_awl);
    cudaGetSymbolAddress((void**)&pwh, g_pwh);
    cudaGetSymbolAddress((void**)&pwl, g_pwl);
    cudaGetSymbolAddress((void**)&xth, g_xth);
    cudaGetSymbolAddress((void**)&xtl, g_xtl);
    cudaGetSymbolAddress((void**)&qth, g_qth);
    cudaGetSymbolAddress((void**)&qtl, g_qtl);
    cudaGetSymbolAddress((void**)&kth, g_kth);
    cudaGetSymbolAddress((void**)&ktl, g_ktl);
    cudaGetSymbolAddress((void**)&sh,  g_sh);
    cudaGetSymbolAddress((void**)&sl,  g_sl);
    cudaGetSymbolAddress((void**)&vh,  g_vh);
    cudaGetSymbolAddress((void**)&vl,  g_vl);
    cudaGetSymbolAddress((void**)&ath, g_ath);
    cudaGetSymbolAddress((void**)&atl, g_atl);

    cudaFuncSetAttribute(gemm_bf16s, cudaFuncAttributeMaxDynamicSharedMemorySize, 98304);

    // ---- conv weight pre-split ----
    {
        auto ws = [&](const float* src, long long off, int n) {
            wsplit_kernel<<<(unsigned)((n + 255) / 256), 256>>>(src, cx.whi + off, cx.wlo + off, n);
        };
        ws(head_w,  0,          LW);
        ws(body_w,  (long long)1 * LW,  16 * LW);
        ws(btail_w, (long long)17 * LW, LW);
        ws(up_w,    (long long)18 * LW, 4 * LW);
        ws(tail_w,  (long long)22 * LW, LW);
        ws(c1_w,    (long long)23 * LW, LW);
        ws(c2_w,    (long long)24 * LW, LW);
    }
    // ---- attention weight transpose-splits ----
    {
        dim3 blk(32, 8);
        for (int i = 0; i < 8; i++) {
            tsplit_kernel<<<dim3(48, 16), blk>>>(qkv_w + (long long)i * 512 * 1536, 512, 1536,
                                                 awh + (long long)i * 1536 * 512,
                                                 awl + (long long)i * 1536 * 512);
            tsplit_kernel<<<dim3(16, 16), blk>>>(proj_w + (long long)i * 512 * 512, 512, 512,
                                                 pwh + (long long)i * 512 * 512,
                                                 pwl + (long long)i * 512 * 512);
        }
    }

    copy_kernel<<<(512 * 1024 + 255) / 256, 256>>>(x, gx, 512 * 1024);

    const float scale = 0.044194173824159216f;  // 512^-0.5
    dim3 blk32(32, 8);

    // ---- 8 self-attention blocks (MMA path) ----
    for (int i = 0; i < 8; i++) {
        // x^T split (1024, 512)
        tsplit_kernel<<<dim3(32, 16), blk32>>>(gx, 512, 1024, xth, xtl);
        // qkv (1536, 1024) = qkvw^T * x^T^T
        gemm_bf16s<<<dim3(16, 12, 1), 256, 98304>>>(
            awh + (long long)i * 1536 * 512, awl + (long long)i * 1536 * 512, 512, 0,
            xth, xtl, 512, 0,
            gqkv, 1024, 0, 0, 1024, 512, 1.f,
            nullptr, nullptr, nullptr, nullptr, nullptr, nullptr, 0, 0);
        // q^T, k^T splits (1024, 512)
        tsplit_kernel<<<dim3(32, 16), blk32>>>(gqkv, 512, 1024, qth, qtl);
        tsplit_kernel<<<dim3(32, 16), blk32>>>(gqkv + 512 * 1024, 512, 1024, kth, ktl);
        // scores S[h](n,m) = scale * q_h^T k_h : batched z=8, K=64
        gemm_bf16s<<<dim3(16, 8, 8), 256, 98304>>>(
            qth, qtl, 512, 64,
            kth, ktl, 512, 64,
            gS, 1024, 1024LL * 1024, 0, 1024, 64, scale,
            nullptr, nullptr, nullptr, nullptr, nullptr, nullptr, 0, 0);
        // softmax + split
        softmax_split<<<1024, 256>>>(gS, sh, sl, 8 * 1024, 1024);
        // v split (512, 1024)
        wsplit_kernel<<<(512 * 1024 + 255) / 256, 256>>>(gqkv + 1024 * 1024, vh, vl, 512 * 1024);
        // att^T(n, h*64+d) = S_h * v_h^T : batched z=8, M=1024, N=64, K=1024
        gemm_bf16s<<<dim3(1, 8, 8), 256, 98304>>>(
            sh, sl, 1024, 1024LL * 1024,
            vh, vl, 1024, 64LL * 1024,
            gatt, 512, 0, 64, 64, 1024, 1.f,
            nullptr, nullptr, nullptr, nullptr, nullptr, nullptr, 0, 0);
        // att^T split
        wsplit_kernel<<<(1024 * 512 + 255) / 256, 256>>>(gatt, ath, atl, 1024 * 512);
        // x += proj^T * att + proj_b
        gemm_bf16s<<<dim3(16, 4, 1), 256, 98304>>>(
            pwh + (long long)i * 512 * 512, pwl + (long long)i * 512 * 512, 512, 0,
            ath, atl, 512, 0,
            gx, 1024, 0, 0, 1024, 512, 1.f,
            proj_b + i * 512, nullptr, nullptr, nullptr, nullptr, gx, 1024, 0);
    }

    // ---- BEV grid transform ----
    grid_sample_kernel<<<(512 * 2500 + 255) / 256, 256>>>(gx, b0);

    // ---- EDSR (pipelined bf16-split GEMM convs) ----
    conv_tc(cx, b0, 0, gh, 512, 50, 50, head_b, 0, 0, 0, 0, nullptr, 0);
    const float* rcur = gh;
    float* bufs[2] = {b1, b2};
    for (int i = 0; i < 8; i++) {
        long long w0 = (long long)(1 + 2 * i) * LW;
        long long w1 = (long long)(2 + 2 * i) * LW;
        conv_tc(cx, rcur, w0, b0, 512, 50, 50, body_b + i * 1024, 0, 0, 0, 0, nullptr, 1);
        float* rnext = bufs[i & 1];
        conv_tc(cx, b0, w1, rnext, 512, 50, 50, body_b + i * 1024 + 512, 0, 0, 0, 0, rcur, 0);
        rcur = rnext;
    }
    conv_tc(cx, rcur, (long long)17 * LW, b1, 512, 50, 50, btail_b, 0, 0, 0, 0, gh, 0);
    conv_tc(cx, b1, (long long)18 * LW, b2, 2048, 50, 50, up_b, 0, 0, 0, 0, nullptr, 0);
    pixel_shuffle_kernel<<<(512 * 10000 + 255) / 256, 256>>>(b2, b0);
    conv_tc(cx, b0, (long long)22 * LW, b1, 512, 100, 100, tail_b, 0, 0, 0, 0, nullptr, 0);

    // ---- classifier ----
    conv_tc(cx, b1, (long long)23 * LW, b0, 512, 100, 100, nullptr, bn1_g, bn1_b, bn1_m, bn1_v, nullptr, 1);
    conv_tc(cx, b0, (long long)24 * LW, b1, 512, 100, 100, nullptr, bn2_g, bn2_b, bn2_m, bn2_v, nullptr, 1);
    conv1x1_sigmoid_kernel<<<(6 * 10000 + 255) / 256, 256>>>(b1, c3_w, c3_b, (float*)d_out);
}

// round 15
// speedup vs baseline: 4.1479x; 1.1673x over previous
#include <cuda_runtime.h>
#include <cuda_bf16.h>
#include <math.h>
#include <stdint.h>

#define CONVK 4608     // 512 * 9
#define LW    2359296  // 512*4608 weight elements per standard conv layer

// ---------------- scratch buffers (device globals; no allocations allowed) ----
__device__ float g_x[512 * 1024];          // token features (C, N)
__device__ float g_qkv[1536 * 1024];       // qkv (3C, N)
__device__ float g_S[8 * 1024 * 1024];     // attention scores scratch (fp32)
__device__ float g_att[1024 * 512];        // att^T (N, C) fp32
__device__ float g_h[512 * 2500];          // EDSR head output (skip)
__device__ float g_b0[512 * 10000];
__device__ float g_b1[512 * 10000];
__device__ float g_b2[512 * 10000];        // up-conv output (2048*2500)

// conv pre-split bf16 planes (K permuted tap-major: k' = tap*512 + ci)
__device__ unsigned short g_whi[25 * LW];
__device__ unsigned short g_wlo[25 * LW];
// activation transposed split planes: (P, 512), channel-contiguous
__device__ unsigned short g_achi[10240 * 512];
__device__ unsigned short g_aclo[10240 * 512];

// attention split planes
__device__ unsigned short g_awh[8 * 1536 * 512], g_awl[8 * 1536 * 512];  // qkv_w^T
__device__ unsigned short g_pwh[8 * 512 * 512],  g_pwl[8 * 512 * 512];   // proj_w^T
__device__ unsigned short g_xth[1024 * 512],     g_xtl[1024 * 512];      // x^T
__device__ unsigned short g_qth[1024 * 512],     g_qtl[1024 * 512];      // q^T
__device__ unsigned short g_kth[1024 * 512],     g_ktl[1024 * 512];      // k^T
__device__ unsigned short g_sh[8 * 1024 * 1024], g_sl[8 * 1024 * 1024];  // softmax(P)
__device__ unsigned short g_vh[512 * 1024],      g_vl[512 * 1024];       // v
__device__ unsigned short g_ath[1024 * 512],     g_atl[1024 * 512];      // att^T

// =================== warp-MMA / async helpers =================================
__device__ __forceinline__ uint32_t smem_u32(const void* p) {
    uint32_t a;
    asm("{ .reg .u64 t; cvta.to.shared.u64 t, %1; cvt.u32.u64 %0, t; }" : "=r"(a) : "l"(p));
    return a;
}
__device__ __forceinline__ void ldsm_x4(uint32_t (&r)[4], uint32_t addr) {
    asm volatile("ldmatrix.sync.aligned.m8n8.x4.shared.b16 {%0,%1,%2,%3}, [%4];"
        : "=r"(r[0]), "=r"(r[1]), "=r"(r[2]), "=r"(r[3]) : "r"(addr));
}
__device__ __forceinline__ void mma16816(float* d, const uint32_t (&a)[4], const uint32_t* b) {
    asm volatile("mma.sync.aligned.m16n8k16.row.col.f32.bf16.bf16.f32 "
        "{%0,%1,%2,%3}, {%4,%5,%6,%7}, {%8,%9}, {%0,%1,%2,%3};"
        : "+f"(d[0]), "+f"(d[1]), "+f"(d[2]), "+f"(d[3])
        : "r"(a[0]), "r"(a[1]), "r"(a[2]), "r"(a[3]), "r"(b[0]), "r"(b[1]));
}
__device__ __forceinline__ void cp16(uint32_t dst, const void* src) {
    asm volatile("cp.async.cg.shared.global [%0], [%1], 16;" :: "r"(dst), "l"(src));
}
// zfill variant: src-size 0 -> whole 16B zero-filled, no global read
__device__ __forceinline__ void cp16z(uint32_t dst, const void* src, int sz) {
    asm volatile("cp.async.cg.shared.global [%0], [%1], 16, %2;" :: "r"(dst), "l"(src), "r"(sz));
}
#define CP_COMMIT() asm volatile("cp.async.commit_group;" ::: "memory")
#define CP_WAIT1()  asm volatile("cp.async.wait_group 1;" ::: "memory")

__device__ __forceinline__ void split_store(float v, unsigned short* hi, unsigned short* lo,
                                            size_t idx) {
    __nv_bfloat16 h = __float2bfloat16(v);
    __nv_bfloat16 l = __float2bfloat16(v - __bfloat162float(h));
    hi[idx] = *reinterpret_cast<unsigned short*>(&h);
    lo[idx] = *reinterpret_cast<unsigned short*>(&l);
}

// =================== split / transpose-split kernels ==========================
__global__ void wsplit_kernel(const float* __restrict__ w,
                              unsigned short* __restrict__ hi,
                              unsigned short* __restrict__ lo, int n)
{
    int i = blockIdx.x * blockDim.x + threadIdx.x;
    if (i >= n) return;
    split_store(w[i], hi, lo, i);
}

// conv weight split with K permutation: out[co][tap*512+ci] = split(w[co][ci*9+tap])
// grid: (18, rows); block 256
__global__ void wsplit_perm(const float* __restrict__ w,
                            unsigned short* __restrict__ hi, unsigned short* __restrict__ lo)
{
    int j = blockIdx.x * 256 + threadIdx.x;   // 0..4607 = k'
    size_t co = blockIdx.y;
    int tap = j >> 9, ci = j & 511;
    float v = w[co * CONVK + (size_t)ci * 9 + tap];
    split_store(v, hi, lo, co * CONVK + j);
}

// in (R,C) row-major fp32 -> out (C,R) split bf16, batched over z
__global__ void tsplit_kernel(const float* __restrict__ in, int R, int C, long long inStride,
                              unsigned short* __restrict__ hi, unsigned short* __restrict__ lo,
                              long long outStride)
{
    in += (long long)blockIdx.z * inStride;
    hi += (long long)blockIdx.z * outStride;
    lo += (long long)blockIdx.z * outStride;
    __shared__ float t[32][33];
    int c0 = blockIdx.x * 32, r0 = blockIdx.y * 32;
    int tx = threadIdx.x, ty = threadIdx.y;   // block (32, 8)
    #pragma unroll
    for (int s = 0; s < 32; s += 8) {
        int r = r0 + ty + s, cc = c0 + tx;
        t[ty + s][tx] = (r < R && cc < C) ? in[(size_t)r * C + cc] : 0.f;
    }
    __syncthreads();
    #pragma unroll
    for (int s = 0; s < 32; s += 8) {
        int orow = c0 + ty + s;   // index in C
        int ocol = r0 + tx;       // index in R
        if (orow < C && ocol < R)
            split_store(t[tx][ty + s], hi, lo, (size_t)orow * R + ocol);
    }
}

// =================== conv GEMM: weights x act_T with on-the-fly 3x3 taps ======
// C(Co, P) = W'(Co, 4608 tap-major) . B where B[p][tap*512+ci] = act[ci][p+off(tap)]
// B staged directly from act_T (P,512) — no materialized im2col.
// 128x64 tile, 72 chunks of 64 (tap fixed per chunk), 2-stage cp.async, 96KB smem.
__global__ __launch_bounds__(256, 2)
void gemm_conv(const unsigned short* __restrict__ Whi, const unsigned short* __restrict__ Wlo,
               const unsigned short* __restrict__ AcH, const unsigned short* __restrict__ AcL,
               int H, int W, float* __restrict__ out, int Co, int P,
               const float* __restrict__ bias,
               const float* __restrict__ bn_g, const float* __restrict__ bn_b,
               const float* __restrict__ bn_m, const float* __restrict__ bn_v,
               const float* __restrict__ resid, int relu)
{
    constexpr uint32_t STG = 49152;
    constexpr uint32_t AHI = 0, ALO = 16384, BHI = 32768, BLO = 40960;
    extern __shared__ char sm[];
    const uint32_t sbase = smem_u32(sm);

    const int tid = threadIdx.x;
    const int lane = tid & 31;
    const int wid = tid >> 5;
    const int wm = wid >> 1;
    const int wn = wid & 1;
    const int m0 = blockIdx.y * 128;
    const int n0 = blockIdx.x * 64;

    const uint32_t xorv = (uint32_t)(lane & 7) << 4;
    const uint32_t a_cg = (uint32_t)(lane >> 4) << 4;
    const uint32_t b_cg = (uint32_t)((lane >> 3) & 1) << 4;
    uint32_t arow[2], brow[2];
    #pragma unroll
    for (int mt = 0; mt < 2; mt++)
        arow[mt] = (uint32_t)(wm * 32 + mt * 16 + (lane & 15)) * 128;
    const int b_r = wn * 32 + (lane & 7) + ((lane >> 4) * 8);
    #pragma unroll
    for (int nt = 0; nt < 2; nt++)
        brow[nt] = (uint32_t)(b_r + nt * 16) * 128;

    const int srow = tid >> 3;          // [0,32)
    const int sc16 = tid & 7;           // [0,8)
    const uint32_t soff_base = (uint32_t)(sc16 * 16);

    // per-thread pixel coords for its 2 B rows
    int py[2], px[2]; bool pv[2];
    #pragma unroll
    for (int s = 0; s < 2; s++) {
        int p = n0 + srow + s * 32;
        pv[s] = p < P;
        int pp = pv[s] ? p : 0;
        py[s] = pp / W;
        px[s] = pp - py[s] * W;
    }

    float acc[2][4][4] = {};

    #define STAGE(SB, CH) do {                                                        \
        uint32_t base = sbase + (uint32_t)(SB) * STG;                                 \
        int k0 = (CH) * 64;                                                           \
        _Pragma("unroll")                                                             \
        for (int s = 0; s < 4; s++) {                                                 \
            int row = srow + s * 32;                                                  \
            uint32_t off = (uint32_t)row * 128 + (soff_base ^ (((uint32_t)row & 7) << 4)); \
            cp16(base + AHI + off, Whi + (size_t)(m0 + row) * CONVK + k0 + sc16 * 8); \
            cp16(base + ALO + off, Wlo + (size_t)(m0 + row) * CONVK + k0 + sc16 * 8); \
        }                                                                             \
        int tap = (CH) >> 3;                                                          \
        int t3 = tap / 3;                                                             \
        int dy = t3 - 1, dx = tap - t3 * 3 - 1;                                       \
        int cib = ((CH) & 7) * 64;                                                    \
        _Pragma("unroll")                                                             \
        for (int s = 0; s < 2; s++) {                                                 \
            int row = srow + s * 32;                                                  \
            uint32_t off = (uint32_t)row * 128 + (soff_base ^ (((uint32_t)row & 7) << 4)); \
            int y2 = py[s] + dy, x2 = px[s] + dx;                                     \
            bool val = pv[s] && (unsigned)y2 < (unsigned)H && (unsigned)x2 < (unsigned)W; \
            size_t sidx = val ? ((size_t)(y2 * W + x2) * 512 + cib + sc16 * 8) : 0;   \
            int sz = val ? 16 : 0;                                                    \
            cp16z(base + BHI + off, AcH + sidx, sz);                                  \
            cp16z(base + BLO + off, AcL + sidx, sz);                                  \
        }                                                                             \
    } while (0)

    STAGE(0, 0);
    CP_COMMIT();

    #pragma unroll 1
    for (int c = 0; c < 72; c++) {
        if (c < 71) STAGE((c + 1) & 1, c + 1);
        CP_COMMIT();
        CP_WAIT1();
        __syncthreads();

        const uint32_t stg = sbase + (uint32_t)(c & 1) * STG;
        #pragma unroll
        for (int kk = 0; kk < 4; kk++) {
            const uint32_t cbA = (((uint32_t)kk << 5) | a_cg) ^ xorv;
            const uint32_t cbB = (((uint32_t)kk << 5) | b_cg) ^ xorv;
            uint32_t ah0[4], ah1[4], al0[4], al1[4];
            uint32_t bh0[4], bh1[4], bl0[4], bl1[4];
            ldsm_x4(ah0, stg + AHI + arow[0] + cbA);
            ldsm_x4(ah1, stg + AHI + arow[1] + cbA);
            ldsm_x4(bh0, stg + BHI + brow[0] + cbB);
            ldsm_x4(bh1, stg + BHI + brow[1] + cbB);
            ldsm_x4(al0, stg + ALO + arow[0] + cbA);
            ldsm_x4(al1, stg + ALO + arow[1] + cbA);
            ldsm_x4(bl0, stg + BLO + brow[0] + cbB);
            ldsm_x4(bl1, stg + BLO + brow[1] + cbB);
            mma16816(acc[0][0], ah0, &bh0[0]);
            mma16816(acc[0][1], ah0, &bh0[2]);
            mma16816(acc[0][2], ah0, &bh1[0]);
            mma16816(acc[0][3], ah0, &bh1[2]);
            mma16816(acc[1][0], ah1, &bh0[0]);
            mma16816(acc[1][1], ah1, &bh0[2]);
            mma16816(acc[1][2], ah1, &bh1[0]);
            mma16816(acc[1][3], ah1, &bh1[2]);
            mma16816(acc[0][0], ah0, &bl0[0]);
            mma16816(acc[0][1], ah0, &bl0[2]);
            mma16816(acc[0][2], ah0, &bl1[0]);
            mma16816(acc[0][3], ah0, &bl1[2]);
            mma16816(acc[1][0], ah1, &bl0[0]);
            mma16816(acc[1][1], ah1, &bl0[2]);
            mma16816(acc[1][2], ah1, &bl1[0]);
            mma16816(acc[1][3], ah1, &bl1[2]);
            mma16816(acc[0][0], al0, &bh0[0]);
            mma16816(acc[0][1], al0, &bh0[2]);
            mma16816(acc[0][2], al0, &bh1[0]);
            mma16816(acc[0][3], al0, &bh1[2]);
            mma16816(acc[1][0], al1, &bh0[0]);
            mma16816(acc[1][1], al1, &bh0[2]);
            mma16816(acc[1][2], al1, &bh1[0]);
            mma16816(acc[1][3], al1, &bh1[2]);
        }
        __syncthreads();
    }

    #pragma unroll
    for (int mt = 0; mt < 2; mt++) {
        #pragma unroll
        for (int nt = 0; nt < 4; nt++) {
            int row = m0 + wm * 32 + mt * 16 + (lane >> 2);
            int col = n0 + wn * 32 + nt * 8 + (lane & 3) * 2;
            if (col >= P) continue;
            #pragma unroll
            for (int half = 0; half < 2; half++) {
                int r = row + half * 8;
                float v0 = acc[mt][nt][half * 2 + 0];
                float v1 = acc[mt][nt][half * 2 + 1];
                if (bias) { v0 += bias[r]; v1 += bias[r]; }
                if (bn_g) {
                    float sc = bn_g[r] * rsqrtf(bn_v[r] + 1e-5f);
                    float sh = bn_b[r] - bn_m[r] * sc;
                    v0 = v0 * sc + sh; v1 = v1 * sc + sh;
                }
                if (resid) {
                    float2 rr = *(const float2*)(resid + (size_t)r * P + col);
                    v0 += rr.x; v1 += rr.y;
                }
                if (relu) { v0 = fmaxf(v0, 0.f); v1 = fmaxf(v1, 0.f); }
                *(float2*)(out + (size_t)r * P + col) = make_float2(v0, v1);
            }
        }
    }
    #undef STAGE
}

// =================== generalized pipelined bf16-split GEMM (attention) ========
__global__ __launch_bounds__(256, 2)
void gemm_bf16s(const unsigned short* __restrict__ Ahi_, const unsigned short* __restrict__ Alo_,
                int lda, long long sA,
                const unsigned short* __restrict__ Bhi_, const unsigned short* __restrict__ Blo_,
                int ldb, long long sB,
                float* __restrict__ out, int ldc, long long sC, int coffC,
                int Ncols, int K, float alpha,
                const float* __restrict__ bias,
                const float* __restrict__ resid, int ldres)
{
    constexpr uint32_t STG = 49152;
    constexpr uint32_t AHI = 0, ALO = 16384, BHI = 32768, BLO = 40960;
    extern __shared__ char sm[];
    const uint32_t sbase = smem_u32(sm);

    const int z = blockIdx.z;
    const unsigned short* Ahi = Ahi_ + (long long)z * sA;
    const unsigned short* Alo = Alo_ + (long long)z * sA;
    const unsigned short* Bhi = Bhi_ + (long long)z * sB;
    const unsigned short* Blo = Blo_ + (long long)z * sB;
    out += (long long)z * sC + (long long)z * coffC;

    const int tid = threadIdx.x;
    const int lane = tid & 31;
    const int wid = tid >> 5;
    const int wm = wid >> 1;
    const int wn = wid & 1;
    const int m0 = blockIdx.y * 128;
    const int n0 = blockIdx.x * 64;
    const int chunks = K >> 6;

    const uint32_t xorv = (uint32_t)(lane & 7) << 4;
    const uint32_t a_cg = (uint32_t)(lane >> 4) << 4;
    const uint32_t b_cg = (uint32_t)((lane >> 3) & 1) << 4;
    uint32_t arow[2], brow[2];
    #pragma unroll
    for (int mt = 0; mt < 2; mt++)
        arow[mt] = (uint32_t)(wm * 32 + mt * 16 + (lane & 15)) * 128;
    const int b_r = wn * 32 + (lane & 7) + ((lane >> 4) * 8);
    #pragma unroll
    for (int nt = 0; nt < 2; nt++)
        brow[nt] = (uint32_t)(b_r + nt * 16) * 128;

    const int srow = tid >> 3;
    const int sc16 = tid & 7;
    const uint32_t soff_base = (uint32_t)(sc16 * 16);

    float acc[2][4][4] = {};

    #define STAGE(SB, K0) do {                                                        \
        uint32_t base = sbase + (uint32_t)(SB) * STG;                                 \
        _Pragma("unroll")                                                             \
        for (int s = 0; s < 4; s++) {                                                 \
            int row = srow + s * 32;                                                  \
            uint32_t off = (uint32_t)row * 128 + (soff_base ^ (((uint32_t)row & 7) << 4)); \
            cp16(base + AHI + off, Ahi + (size_t)(m0 + row) * lda + (K0) + sc16 * 8); \
            cp16(base + ALO + off, Alo + (size_t)(m0 + row) * lda + (K0) + sc16 * 8); \
        }                                                                             \
        _Pragma("unroll")                                                             \
        for (int s = 0; s < 2; s++) {                                                 \
            int row = srow + s * 32;                                                  \
            uint32_t off = (uint32_t)row * 128 + (soff_base ^ (((uint32_t)row & 7) << 4)); \
            cp16(base + BHI + off, Bhi + (size_t)(n0 + row) * ldb + (K0) + sc16 * 8); \
            cp16(base + BLO + off, Blo + (size_t)(n0 + row) * ldb + (K0) + sc16 * 8); \
        }                                                                             \
    } while (0)

    STAGE(0, 0);
    CP_COMMIT();

    #pragma unroll 1
    for (int c = 0; c < chunks; c++) {
        if (c < chunks - 1) STAGE((c + 1) & 1, (c + 1) * 64);
        CP_COMMIT();
        CP_WAIT1();
        __syncthreads();

        const uint32_t stg = sbase + (uint32_t)(c & 1) * STG;
        #pragma unroll
        for (int kk = 0; kk < 4; kk++) {
            const uint32_t cbA = (((uint32_t)kk << 5) | a_cg) ^ xorv;
            const uint32_t cbB = (((uint32_t)kk << 5) | b_cg) ^ xorv;
            uint32_t ah0[4], ah1[4], al0[4], al1[4];
            uint32_t bh0[4], bh1[4], bl0[4], bl1[4];
            ldsm_x4(ah0, stg + AHI + arow[0] + cbA);
            ldsm_x4(ah1, stg + AHI + arow[1] + cbA);
            ldsm_x4(bh0, stg + BHI + brow[0] + cbB);
            ldsm_x4(bh1, stg + BHI + brow[1] + cbB);
            ldsm_x4(al0, stg + ALO + arow[0] + cbA);
            ldsm_x4(al1, stg + ALO + arow[1] + cbA);
            ldsm_x4(bl0, stg + BLO + brow[0] + cbB);
            ldsm_x4(bl1, stg + BLO + brow[1] + cbB);
            mma16816(acc[0][0], ah0, &bh0[0]);
            mma16816(acc[0][1], ah0, &bh0[2]);
            mma16816(acc[0][2], ah0, &bh1[0]);
            mma16816(acc[0][3], ah0, &bh1[2]);
            mma16816(acc[1][0], ah1, &bh0[0]);
            mma16816(acc[1][1], ah1, &bh0[2]);
            mma16816(acc[1][2], ah1, &bh1[0]);
            mma16816(acc[1][3], ah1, &bh1[2]);
            mma16816(acc[0][0], ah0, &bl0[0]);
            mma16816(acc[0][1], ah0, &bl0[2]);
            mma16816(acc[0][2], ah0, &bl1[0]);
            mma16816(acc[0][3], ah0, &bl1[2]);
            mma16816(acc[1][0], ah1, &bl0[0]);
            mma16816(acc[1][1], ah1, &bl0[2]);
            mma16816(acc[1][2], ah1, &bl1[0]);
            mma16816(acc[1][3], ah1, &bl1[2]);
            mma16816(acc[0][0], al0, &bh0[0]);
            mma16816(acc[0][1], al0, &bh0[2]);
            mma16816(acc[0][2], al0, &bh1[0]);
            mma16816(acc[0][3], al0, &bh1[2]);
            mma16816(acc[1][0], al1, &bh0[0]);
            mma16816(acc[1][1], al1, &bh0[2]);
            mma16816(acc[1][2], al1, &bh1[0]);
            mma16816(acc[1][3], al1, &bh1[2]);
        }
        __syncthreads();
    }

    #pragma unroll
    for (int mt = 0; mt < 2; mt++) {
        #pragma unroll
        for (int nt = 0; nt < 4; nt++) {
            int row = m0 + wm * 32 + mt * 16 + (lane >> 2);
            int col = n0 + wn * 32 + nt * 8 + (lane & 3) * 2;
            if (col >= Ncols) continue;
            #pragma unroll
            for (int half = 0; half < 2; half++) {
                int r = row + half * 8;
                float v0 = acc[mt][nt][half * 2 + 0] * alpha;
                float v1 = acc[mt][nt][half * 2 + 1] * alpha;
                if (bias) { v0 += bias[r]; v1 += bias[r]; }
                if (resid) {
                    float2 rr = *(const float2*)(resid + (size_t)r * ldres + col);
                    v0 += rr.x; v1 += rr.y;
                }
                *(float2*)(out + (size_t)r * ldc + col) = make_float2(v0, v1);
            }
        }
    }
    #undef STAGE
}

// ---------------- softmax (one warp per row) -> split bf16 output -------------
__global__ void softmax_split(float* __restrict__ S,
                              unsigned short* __restrict__ hi, unsigned short* __restrict__ lo,
                              int rows, int cols)
{
    int warp = (blockIdx.x * blockDim.x + threadIdx.x) >> 5;
    int lane = threadIdx.x & 31;
    if (warp >= rows) return;
    float* row = S + (long long)warp * cols;
    unsigned short* ho = hi + (long long)warp * cols;
    unsigned short* lo_ = lo + (long long)warp * cols;
    float mx = -INFINITY;
    for (int i = lane; i < cols; i += 32) mx = fmaxf(mx, row[i]);
    #pragma unroll
    for (int o = 16; o; o >>= 1) mx = fmaxf(mx, __shfl_xor_sync(0xffffffffu, mx, o));
    float sum = 0.f;
    for (int i = lane; i < cols; i += 32) {
        float e = __expf(row[i] - mx);
        row[i] = e;
        sum += e;
    }
    #pragma unroll
    for (int o = 16; o; o >>= 1) sum += __shfl_xor_sync(0xffffffffu, sum, o);
    float inv = 1.f / sum;
    for (int i = lane; i < cols; i += 32) {
        float v = row[i] * inv;
        __nv_bfloat16 h = __float2bfloat16(v);
        __nv_bfloat16 l = __float2bfloat16(v - __bfloat162float(h));
        ho[i] = *reinterpret_cast<unsigned short*>(&h);
        lo_[i] = *reinterpret_cast<unsigned short*>(&l);
    }
}

// ---------------- BEV grid transform ------------------------------------------
__global__ void grid_sample_kernel(const float* __restrict__ in, float* __restrict__ out)
{
    int idx = blockIdx.x * blockDim.x + threadIdx.x;
    if (idx >= 512 * 50 * 50) return;
    int i = idx % 50;
    int j = (idx / 50) % 50;
    int c = idx / 2500;
    int iy = __float2int_rn(0.625f * (float)j + 0.1875f);
    int ix = __float2int_rn(0.625f * (float)i + 0.1875f);
    out[idx] = in[c * 1024 + iy * 32 + ix];
}

// ---------------- pixel shuffle r=2 -------------------------------------------
__global__ void pixel_shuffle_kernel(const float* __restrict__ in, float* __restrict__ out)
{
    int idx = blockIdx.x * blockDim.x + threadIdx.x;
    if (idx >= 512 * 100 * 100) return;
    int ox = idx % 100;
    int oy = (idx / 100) % 100;
    int c = idx / 10000;
    int y = oy >> 1, ry = oy & 1;
    int x = ox >> 1, rx = ox & 1;
    out[idx] = in[(c * 4 + ry * 2 + rx) * 2500 + y * 50 + x];
}

// ---------------- final 1x1 conv (512 -> 6) + sigmoid -------------------------
__global__ void conv1x1_sigmoid_kernel(
    const float* __restrict__ in, const float* __restrict__ w,
    const float* __restrict__ b, float* __restrict__ out)
{
    int idx = blockIdx.x * blockDim.x + threadIdx.x;
    if (idx >= 6 * 10000) return;
    int p = idx % 10000;
    int cls = idx / 10000;
    float acc = b[cls];
    const float* wp = w + cls * 512;
    #pragma unroll 4
    for (int c = 0; c < 512; c++)
        acc = fmaf(in[c * 10000 + p], wp[c], acc);
    out[idx] = 1.f / (1.f + __expf(-acc));
}

__global__ void copy_kernel(const float* __restrict__ in, float* __restrict__ out, int n)
{
    int i = blockIdx.x * blockDim.x + threadIdx.x;
    if (i < n) out[i] = in[i];
}

// ---------------- host orchestration -----------------------------------------
struct ConvCtx {
    unsigned short *whi, *wlo, *achi, *aclo;
};

static void conv_tc(const ConvCtx& cx, const float* in, long long woff, float* out,
                    int Co, int H, int W,
                    const float* bias,
                    const float* g, const float* bb, const float* m, const float* v,
                    const float* res, int relu)
{
    int P = H * W;
    // transpose-split activation (512, P) -> act_T (P, 512)
    tsplit_kernel<<<dim3((P + 31) / 32, 16, 1), dim3(32, 8)>>>(in, 512, P, 0,
                                                               cx.achi, cx.aclo, 0);
    dim3 grid((unsigned)((P + 63) / 64), (unsigned)(Co / 128));
    gemm_conv<<<grid, 256, 98304>>>(cx.whi + woff, cx.wlo + woff, cx.achi, cx.aclo,
                                    H, W, out, Co, P, bias, g, bb, m, v, res, relu);
}

extern "C" void kernel_launch(void* const* d_in, const int* in_sizes, int n_in,
                              void* d_out, int out_size)
{
    const float* x       = (const float*)d_in[0];
    const float* qkv_w   = (const float*)d_in[1];
    const float* proj_w  = (const float*)d_in[2];
    const float* proj_b  = (const float*)d_in[3];
    const float* head_w  = (const float*)d_in[4];
    const float* head_b  = (const float*)d_in[5];
    const float* body_w  = (const float*)d_in[6];
    const float* body_b  = (const float*)d_in[7];
    const float* btail_w = (const float*)d_in[8];
    const float* btail_b = (const float*)d_in[9];
    const float* up_w    = (const float*)d_in[10];
    const float* up_b    = (const float*)d_in[11];
    const float* tail_w  = (const float*)d_in[12];
    const float* tail_b  = (const float*)d_in[13];
    const float* c1_w    = (const float*)d_in[14];
    const float* bn1_g   = (const float*)d_in[15];
    const float* bn1_b   = (const float*)d_in[16];
    const float* bn1_m   = (const float*)d_in[17];
    const float* bn1_v   = (const float*)d_in[18];
    const float* c2_w    = (const float*)d_in[19];
    const float* bn2_g   = (const float*)d_in[20];
    const float* bn2_b   = (const float*)d_in[21];
    const float* bn2_m   = (const float*)d_in[22];
    const float* bn2_v   = (const float*)d_in[23];
    const float* c3_w    = (const float*)d_in[24];
    const float* c3_b    = (const float*)d_in[25];

    float *gx, *gqkv, *gS, *gatt, *gh, *b0, *b1, *b2;
    cudaGetSymbolAddress((void**)&gx,   g_x);
    cudaGetSymbolAddress((void**)&gqkv, g_qkv);
    cudaGetSymbolAddress((void**)&gS,   g_S);
    cudaGetSymbolAddress((void**)&gatt, g_att);
    cudaGetSymbolAddress((void**)&gh,   g_h);
    cudaGetSymbolAddress((void**)&b0,   g_b0);
    cudaGetSymbolAddress((void**)&b1,   g_b1);
    cudaGetSymbolAddress((void**)&b2,   g_b2);

    ConvCtx cx;
    cudaGetSymbolAddress((void**)&cx.whi,  g_whi);
    cudaGetSymbolAddress((void**)&cx.wlo,  g_wlo);
    cudaGetSymbolAddress((void**)&cx.achi, g_achi);
    cudaGetSymbolAddress((void**)&cx.aclo, g_aclo);

    unsigned short *awh, *awl, *pwh, *pwl, *xth, *xtl, *qth, *qtl, *kth, *ktl;
    unsigned short *sh, *sl, *vh, *vl, *ath, *atl;
    cudaGetSymbolAddress((void**)&awh, g_awh);
    cudaGetSymbolAddress((void**)&awl, g_awl);
    cudaGetSymbolAddress((void**)&pwh, g_pwh);
    cudaGetSymbolAddress((void**)&pwl, g_pwl);
    cudaGetSymbolAddress((void**)&xth, g_xth);
    cudaGetSymbolAddress((void**)&xtl, g_xtl);
    cudaGetSymbolAddress((void**)&qth, g_qth);
    cudaGetSymbolAddress((void**)&qtl, g_qtl);
    cudaGetSymbolAddress((void**)&kth, g_kth);
    cudaGetSymbolAddress((void**)&ktl, g_ktl);
    cudaGetSymbolAddress((void**)&sh,  g_sh);
    cudaGetSymbolAddress((void**)&sl,  g_sl);
    cudaGetSymbolAddress((void**)&vh,  g_vh);
    cudaGetSymbolAddress((void**)&vl,  g_vl);
    cudaGetSymbolAddress((void**)&ath, g_ath);
    cudaGetSymbolAddress((void**)&atl, g_atl);

    cudaFuncSetAttribute(gemm_bf16s, cudaFuncAttributeMaxDynamicSharedMemorySize, 98304);
    cudaFuncSetAttribute(gemm_conv,  cudaFuncAttributeMaxDynamicSharedMemorySize, 98304);

    // ---- conv weight pre-split with tap-major K permutation ----
    {
        auto ws = [&](const float* src, long long off, int rows) {
            wsplit_perm<<<dim3(18, (unsigned)rows), 256>>>(src, cx.whi + off, cx.wlo + off);
        };
        ws(head_w,  0,                 512);
        ws(body_w,  (long long)1 * LW, 16 * 512);
        ws(btail_w, (long long)17 * LW, 512);
        ws(up_w,    (long long)18 * LW, 2048);
        ws(tail_w,  (long long)22 * LW, 512);
        ws(c1_w,    (long long)23 * LW, 512);
        ws(c2_w,    (long long)24 * LW, 512);
    }
    // ---- attention weight transpose-splits (batched over 8 blocks) ----
    {
        dim3 blk(32, 8);
        tsplit_kernel<<<dim3(48, 16, 8), blk>>>(qkv_w, 512, 1536, 512LL * 1536,
                                                awh, awl, 1536LL * 512);
        tsplit_kernel<<<dim3(16, 16, 8), blk>>>(proj_w, 512, 512, 512LL * 512,
                                                pwh, pwl, 512LL * 512);
    }

    copy_kernel<<<(512 * 1024 + 255) / 256, 256>>>(x, gx, 512 * 1024);

    const float scale = 0.044194173824159216f;  // 512^-0.5
    dim3 blk32(32, 8);

    // ---- 8 self-attention blocks (MMA path) ----
    for (int i = 0; i < 8; i++) {
        tsplit_kernel<<<dim3(32, 16, 1), blk32>>>(gx, 512, 1024, 0, xth, xtl, 0);
        gemm_bf16s<<<dim3(16, 12, 1), 256, 98304>>>(
            awh + (long long)i * 1536 * 512, awl + (long long)i * 1536 * 512, 512, 0,
            xth, xtl, 512, 0,
            gqkv, 1024, 0, 0, 1024, 512, 1.f, nullptr, nullptr, 0);
        tsplit_kernel<<<dim3(32, 16, 1), blk32>>>(gqkv, 512, 1024, 0, qth, qtl, 0);
        tsplit_kernel<<<dim3(32, 16, 1), blk32>>>(gqkv + 512 * 1024, 512, 1024, 0, kth, ktl, 0);
        gemm_bf16s<<<dim3(16, 8, 8), 256, 98304>>>(
            qth, qtl, 512, 64,
            kth, ktl, 512, 64,
            gS, 1024, 1024LL * 1024, 0, 1024, 64, scale, nullptr, nullptr, 0);
        softmax_split<<<1024, 256>>>(gS, sh, sl, 8 * 1024, 1024);
        wsplit_kernel<<<(512 * 1024 + 255) / 256, 256>>>(gqkv + 1024 * 1024, vh, vl, 512 * 1024);
        gemm_bf16s<<<dim3(1, 8, 8), 256, 98304>>>(
            sh, sl, 1024, 1024LL * 1024,
            vh, vl, 1024, 64LL * 1024,
            gatt, 512, 0, 64, 64, 1024, 1.f, nullptr, nullptr, 0);
        wsplit_kernel<<<(1024 * 512 + 255) / 256, 256>>>(gatt, ath, atl, 1024 * 512);
        gemm_bf16s<<<dim3(16, 4, 1), 256, 98304>>>(
            pwh + (long long)i * 512 * 512, pwl + (long long)i * 512 * 512, 512, 0,
            ath, atl, 512, 0,
            gx, 1024, 0, 0, 1024, 512, 1.f,
            proj_b + i * 512, gx, 1024);
    }

    // ---- BEV grid transform ----
    grid_sample_kernel<<<(512 * 2500 + 255) / 256, 256>>>(gx, b0);

    // ---- EDSR (direct-staged bf16-split convs) ----
    conv_tc(cx, b0, 0, gh, 512, 50, 50, head_b, 0, 0, 0, 0, nullptr, 0);
    const float* rcur = gh;
    float* bufs[2] = {b1, b2};
    for (int i = 0; i < 8; i++) {
        long long w0 = (long long)(1 + 2 * i) * LW;
        long long w1 = (long long)(2 + 2 * i) * LW;
        conv_tc(cx, rcur, w0, b0, 512, 50, 50, body_b + i * 1024, 0, 0, 0, 0, nullptr, 1);
        float* rnext = bufs[i & 1];
        conv_tc(cx, b0, w1, rnext, 512, 50, 50, body_b + i * 1024 + 512, 0, 0, 0, 0, rcur, 0);
        rcur = rnext;
    }
    conv_tc(cx, rcur, (long long)17 * LW, b1, 512, 50, 50, btail_b, 0, 0, 0, 0, gh, 0);
    conv_tc(cx, b1, (long long)18 * LW, b2, 2048, 50, 50, up_b, 0, 0, 0, 0, nullptr, 0);
    pixel_shuffle_kernel<<<(512 * 10000 + 255) / 256, 256>>>(b2, b0);
    conv_tc(cx, b0, (long long)22 * LW, b1, 512, 100, 100, tail_b, 0, 0, 0, 0, nullptr, 0);

    // ---- classifier ----
    conv_tc(cx, b1, (long long)23 * LW, b0, 512, 100, 100, nullptr, bn1_g, bn1_b, bn1_m, bn1_v, nullptr, 1);
    conv_tc(cx, b0, (long long)24 * LW, b1, 512, 100, 100, nullptr, bn2_g, bn2_b, bn2_m, bn2_v, nullptr, 1);
    conv1x1_sigmoid_kernel<<<(6 * 10000 + 255) / 256, 256>>>(b1, c3_w, c3_b, (float*)d_out);
}

// round 17
// speedup vs baseline: 4.6576x; 1.1229x over previous
#include <cuda_runtime.h>
#include <cuda_bf16.h>
#include <math.h>
#include <stdint.h>

#define CONVK 4608     // 512 * 9
#define LW    2359296  // 512*4608 weight elements per standard conv layer

// ---------------- scratch buffers (device globals; no allocations allowed) ----
__device__ float g_x[512 * 1024];          // token features (C, N)
__device__ float g_qkv[1536 * 1024];       // qkv (3C, N)
__device__ float g_S[8 * 1024 * 1024];     // attention scores scratch (fp32)
__device__ float g_h[512 * 2500];          // EDSR head output (skip)
__device__ float g_b0[512 * 10000];
__device__ float g_b1[512 * 10000];
__device__ float g_b2[512 * 10000];        // up-conv output (2048*2500)
__device__ float g_part[2 * 512 * 2560];   // split-K partials (conv: 2x512x2560, PV: 4x1024x512)

// conv pre-split bf16 planes (K permuted tap-major: k' = tap*512 + ci)
__device__ unsigned short g_whi[25 * LW];
__device__ unsigned short g_wlo[25 * LW];
// activation transposed split planes: (P, 512), channel-contiguous
__device__ unsigned short g_achi[10240 * 512];
__device__ unsigned short g_aclo[10240 * 512];

// attention split planes
__device__ unsigned short g_awh[8 * 1536 * 512], g_awl[8 * 1536 * 512];  // qkv_w^T
__device__ unsigned short g_pwh[8 * 512 * 512],  g_pwl[8 * 512 * 512];   // proj_w^T
__device__ unsigned short g_xth[1024 * 512],     g_xtl[1024 * 512];      // x^T
__device__ unsigned short g_qth[1024 * 512],     g_qtl[1024 * 512];      // q^T
__device__ unsigned short g_kth[1024 * 512],     g_ktl[1024 * 512];      // k^T
__device__ unsigned short g_sh[8 * 1024 * 1024], g_sl[8 * 1024 * 1024];  // softmax(P)
__device__ unsigned short g_vh[512 * 1024],      g_vl[512 * 1024];       // v
__device__ unsigned short g_ath[1024 * 512],     g_atl[1024 * 512];      // att^T

// =================== warp-MMA / async helpers =================================
__device__ __forceinline__ uint32_t smem_u32(const void* p) {
    uint32_t a;
    asm("{ .reg .u64 t; cvta.to.shared.u64 t, %1; cvt.u32.u64 %0, t; }" : "=r"(a) : "l"(p));
    return a;
}
__device__ __forceinline__ void ldsm_x4(uint32_t (&r)[4], uint32_t addr) {
    asm volatile("ldmatrix.sync.aligned.m8n8.x4.shared.b16 {%0,%1,%2,%3}, [%4];"
        : "=r"(r[0]), "=r"(r[1]), "=r"(r[2]), "=r"(r[3]) : "r"(addr));
}
__device__ __forceinline__ void mma16816(float* d, const uint32_t (&a)[4], const uint32_t* b) {
    asm volatile("mma.sync.aligned.m16n8k16.row.col.f32.bf16.bf16.f32 "
        "{%0,%1,%2,%3}, {%4,%5,%6,%7}, {%8,%9}, {%0,%1,%2,%3};"
        : "+f"(d[0]), "+f"(d[1]), "+f"(d[2]), "+f"(d[3])
        : "r"(a[0]), "r"(a[1]), "r"(a[2]), "r"(a[3]), "r"(b[0]), "r"(b[1]));
}
__device__ __forceinline__ void cp16(uint32_t dst, const void* src) {
    asm volatile("cp.async.cg.shared.global [%0], [%1], 16;" :: "r"(dst), "l"(src));
}
__device__ __forceinline__ void cp16z(uint32_t dst, const void* src, int sz) {
    asm volatile("cp.async.cg.shared.global [%0], [%1], 16, %2;" :: "r"(dst), "l"(src), "r"(sz));
}
#define CP_COMMIT() asm volatile("cp.async.commit_group;" ::: "memory")
#define CP_WAIT1()  asm volatile("cp.async.wait_group 1;" ::: "memory")
#define CP_WAIT0()  asm volatile("cp.async.wait_group 0;" ::: "memory")

__device__ __forceinline__ void split_store(float v, unsigned short* hi, unsigned short* lo,
                                            size_t idx) {
    __nv_bfloat16 h = __float2bfloat16(v);
    __nv_bfloat16 l = __float2bfloat16(v - __bfloat162float(h));
    hi[idx] = *reinterpret_cast<unsigned short*>(&h);
    lo[idx] = *reinterpret_cast<unsigned short*>(&l);
}

// =================== split / transpose-split kernels ==========================
__global__ void wsplit_kernel(const float* __restrict__ w,
                              unsigned short* __restrict__ hi,
                              unsigned short* __restrict__ lo, int n)
{
    int i = blockIdx.x * blockDim.x + threadIdx.x;
    if (i >= n) return;
    split_store(w[i], hi, lo, i);
}

// conv weight split with K permutation: out[co][tap*512+ci] = split(w[co][ci*9+tap])
__global__ void wsplit_perm(const float* __restrict__ w,
                            unsigned short* __restrict__ hi, unsigned short* __restrict__ lo)
{
    int j = blockIdx.x * 256 + threadIdx.x;   // 0..4607 = k'
    size_t co = blockIdx.y;
    int tap = j >> 9, ci = j & 511;
    float v = w[co * CONVK + (size_t)ci * 9 + tap];
    split_store(v, hi, lo, co * CONVK + j);
}

// in (R,C) row-major fp32 -> out (C,R) split bf16, batched over z
__global__ void tsplit_kernel(const float* __restrict__ in, int R, int C, long long inStride,
                              unsigned short* __restrict__ hi, unsigned short* __restrict__ lo,
                              long long outStride)
{
    in += (long long)blockIdx.z * inStride;
    hi += (long long)blockIdx.z * outStride;
    lo += (long long)blockIdx.z * outStride;
    __shared__ float t[32][33];
    int c0 = blockIdx.x * 32, r0 = blockIdx.y * 32;
    int tx = threadIdx.x, ty = threadIdx.y;   // block (32, 8)
    #pragma unroll
    for (int s = 0; s < 32; s += 8) {
        int r = r0 + ty + s, cc = c0 + tx;
        t[ty + s][tx] = (r < R && cc < C) ? in[(size_t)r * C + cc] : 0.f;
    }
    __syncthreads();
    #pragma unroll
    for (int s = 0; s < 32; s += 8) {
        int orow = c0 + ty + s;
        int ocol = r0 + tx;
        if (orow < C && ocol < R)
            split_store(t[tx][ty + s], hi, lo, (size_t)orow * R + ocol);
    }
}

// =================== conv GEMM: weights x act_T with on-the-fly 3x3 taps ======
// If part != null: split-K mode, blockIdx.z owns chunks [z*nch, (z+1)*nch), writes
// raw fp32 partials to part + z*512*2560 (row stride 2560); epilogue deferred.
__global__ __launch_bounds__(256, 2)
void gemm_conv(const unsigned short* __restrict__ Whi, const unsigned short* __restrict__ Wlo,
               const unsigned short* __restrict__ AcH, const unsigned short* __restrict__ AcL,
               int H, int W, float* __restrict__ out, int Co, int P,
               const float* __restrict__ bias,
               const float* __restrict__ bn_g, const float* __restrict__ bn_b,
               const float* __restrict__ bn_m, const float* __restrict__ bn_v,
               const float* __restrict__ resid, int relu,
               int nch, float* __restrict__ part)
{
    constexpr uint32_t STG = 49152;
    constexpr uint32_t AHI = 0, ALO = 16384, BHI = 32768, BLO = 40960;
    extern __shared__ char sm[];
    const uint32_t sbase = smem_u32(sm);

    const int tid = threadIdx.x;
    const int lane = tid & 31;
    const int wid = tid >> 5;
    const int wm = wid >> 1;
    const int wn = wid & 1;
    const int m0 = blockIdx.y * 128;
    const int n0 = blockIdx.x * 64;
    const int chunk0 = blockIdx.z * nch;

    const uint32_t xorv = (uint32_t)(lane & 7) << 4;
    const uint32_t a_cg = (uint32_t)(lane >> 4) << 4;
    const uint32_t b_cg = (uint32_t)((lane >> 3) & 1) << 4;
    uint32_t arow[2], brow[2];
    #pragma unroll
    for (int mt = 0; mt < 2; mt++)
        arow[mt] = (uint32_t)(wm * 32 + mt * 16 + (lane & 15)) * 128;
    const int b_r = wn * 32 + (lane & 7) + ((lane >> 4) * 8);
    #pragma unroll
    for (int nt = 0; nt < 2; nt++)
        brow[nt] = (uint32_t)(b_r + nt * 16) * 128;

    const int srow = tid >> 3;
    const int sc16 = tid & 7;
    const uint32_t soff_base = (uint32_t)(sc16 * 16);

    int py[2], px[2]; bool pv[2];
    #pragma unroll
    for (int s = 0; s < 2; s++) {
        int p = n0 + srow + s * 32;
        pv[s] = p < P;
        int pp = pv[s] ? p : 0;
        py[s] = pp / W;
        px[s] = pp - py[s] * W;
    }

    float acc[2][4][4] = {};

    #define STAGE(SB, CH) do {                                                        \
        uint32_t base = sbase + (uint32_t)(SB) * STG;                                 \
        int k0 = (CH) * 64;                                                           \
        _Pragma("unroll")                                                             \
        for (int s = 0; s < 4; s++) {                                                 \
            int row = srow + s * 32;                                                  \
            uint32_t off = (uint32_t)row * 128 + (soff_base ^ (((uint32_t)row & 7) << 4)); \
            cp16(base + AHI + off, Whi + (size_t)(m0 + row) * CONVK + k0 + sc16 * 8); \
            cp16(base + ALO + off, Wlo + (size_t)(m0 + row) * CONVK + k0 + sc16 * 8); \
        }                                                                             \
        int tap = (CH) >> 3;                                                          \
        int t3 = tap / 3;                                                             \
        int dy = t3 - 1, dx = tap - t3 * 3 - 1;                                       \
        int cib = ((CH) & 7) * 64;                                                    \
        _Pragma("unroll")                                                             \
        for (int s = 0; s < 2; s++) {                                                 \
            int row = srow + s * 32;                                                  \
            uint32_t off = (uint32_t)row * 128 + (soff_base ^ (((uint32_t)row & 7) << 4)); \
            int y2 = py[s] + dy, x2 = px[s] + dx;                                     \
            bool val = pv[s] && (unsigned)y2 < (unsigned)H && (unsigned)x2 < (unsigned)W; \
            size_t sidx = val ? ((size_t)(y2 * W + x2) * 512 + cib + sc16 * 8) : 0;   \
            int sz = val ? 16 : 0;                                                    \
            cp16z(base + BHI + off, AcH + sidx, sz);                                  \
            cp16z(base + BLO + off, AcL + sidx, sz);                                  \
        }                                                                             \
    } while (0)

    STAGE(0, chunk0);
    CP_COMMIT();

    #pragma unroll 1
    for (int c = 0; c < nch; c++) {
        if (c < nch - 1) { STAGE((c + 1) & 1, chunk0 + c + 1); CP_COMMIT(); CP_WAIT1(); }
        else             { CP_WAIT0(); }
        __syncthreads();

        const uint32_t stg = sbase + (uint32_t)(c & 1) * STG;
        #pragma unroll
        for (int kk = 0; kk < 4; kk++) {
            const uint32_t cbA = (((uint32_t)kk << 5) | a_cg) ^ xorv;
            const uint32_t cbB = (((uint32_t)kk << 5) | b_cg) ^ xorv;
            uint32_t ah0[4], ah1[4], al0[4], al1[4];
            uint32_t bh0[4], bh1[4], bl0[4], bl1[4];
            ldsm_x4(ah0, stg + AHI + arow[0] + cbA);
            ldsm_x4(ah1, stg + AHI + arow[1] + cbA);
            ldsm_x4(bh0, stg + BHI + brow[0] + cbB);
            ldsm_x4(bh1, stg + BHI + brow[1] + cbB);
            ldsm_x4(al0, stg + ALO + arow[0] + cbA);
            ldsm_x4(al1, stg + ALO + arow[1] + cbA);
            ldsm_x4(bl0, stg + BLO + brow[0] + cbB);
            ldsm_x4(bl1, stg + BLO + brow[1] + cbB);
            mma16816(acc[0][0], ah0, &bh0[0]);
            mma16816(acc[0][1], ah0, &bh0[2]);
            mma16816(acc[0][2], ah0, &bh1[0]);
            mma16816(acc[0][3], ah0, &bh1[2]);
            mma16816(acc[1][0], ah1, &bh0[0]);
            mma16816(acc[1][1], ah1, &bh0[2]);
            mma16816(acc[1][2], ah1, &bh1[0]);
            mma16816(acc[1][3], ah1, &bh1[2]);
            mma16816(acc[0][0], ah0, &bl0[0]);
            mma16816(acc[0][1], ah0, &bl0[2]);
            mma16816(acc[0][2], ah0, &bl1[0]);
            mma16816(acc[0][3], ah0, &bl1[2]);
            mma16816(acc[1][0], ah1, &bl0[0]);
            mma16816(acc[1][1], ah1, &bl0[2]);
            mma16816(acc[1][2], ah1, &bl1[0]);
            mma16816(acc[1][3], ah1, &bl1[2]);
            mma16816(acc[0][0], al0, &bh0[0]);
            mma16816(acc[0][1], al0, &bh0[2]);
            mma16816(acc[0][2], al0, &bh1[0]);
            mma16816(acc[0][3], al0, &bh1[2]);
            mma16816(acc[1][0], al1, &bh0[0]);
            mma16816(acc[1][1], al1, &bh0[2]);
            mma16816(acc[1][2], al1, &bh1[0]);
            mma16816(acc[1][3], al1, &bh1[2]);
        }
        __syncthreads();
    }

    if (part) {
        float* po = part + (size_t)blockIdx.z * (512 * 2560);
        #pragma unroll
        for (int mt = 0; mt < 2; mt++)
            #pragma unroll
            for (int nt = 0; nt < 4; nt++) {
                int row = m0 + wm * 32 + mt * 16 + (lane >> 2);
                int col = n0 + wn * 32 + nt * 8 + (lane & 3) * 2;
                #pragma unroll
                for (int half = 0; half < 2; half++) {
                    int r = row + half * 8;
                    *(float2*)(po + (size_t)r * 2560 + col) =
                        make_float2(acc[mt][nt][half * 2 + 0], acc[mt][nt][half * 2 + 1]);
                }
            }
        return;
    }

    #pragma unroll
    for (int mt = 0; mt < 2; mt++) {
        #pragma unroll
        for (int nt = 0; nt < 4; nt++) {
            int row = m0 + wm * 32 + mt * 16 + (lane >> 2);
            int col = n0 + wn * 32 + nt * 8 + (lane & 3) * 2;
            if (col >= P) continue;
            #pragma unroll
            for (int half = 0; half < 2; half++) {
                int r = row + half * 8;
                float v0 = acc[mt][nt][half * 2 + 0];
                float v1 = acc[mt][nt][half * 2 + 1];
                if (bias) { v0 += bias[r]; v1 += bias[r]; }
                if (bn_g) {
                    float sc = bn_g[r] * rsqrtf(bn_v[r] + 1e-5f);
                    float sh = bn_b[r] - bn_m[r] * sc;
                    v0 = v0 * sc + sh; v1 = v1 * sc + sh;
                }
                if (resid) {
                    float2 rr = *(const float2*)(resid + (size_t)r * P + col);
                    v0 += rr.x; v1 += rr.y;
                }
                if (relu) { v0 = fmaxf(v0, 0.f); v1 = fmaxf(v1, 0.f); }
                *(float2*)(out + (size_t)r * P + col) = make_float2(v0, v1);
            }
        }
    }
    #undef STAGE
}

// conv split-K finalize: out = epi(part0 + part1)
__global__ void conv_fin(const float* __restrict__ part, float* __restrict__ out, int P,
                         const float* __restrict__ bias,
                         const float* __restrict__ resid, int relu)
{
    int idx = blockIdx.x * blockDim.x + threadIdx.x;
    if (idx >= 512 * P) return;
    int r = idx / P, p = idx - r * P;
    size_t pi = (size_t)r * 2560 + p;
    float v = part[pi] + part[512 * 2560 + pi];
    if (bias) v += bias[r];
    if (resid) v += resid[idx];
    if (relu) v = fmaxf(v, 0.f);
    out[idx] = v;
}

// =================== generalized pipelined bf16-split GEMM (attention) ========
// ksplit>1: blockIdx.z = zbatch*ksplit + kz; writes raw partials to
// part + kz*partStride (+ zbatch offsets); epilogue deferred.
__global__ __launch_bounds__(256, 2)
void gemm_bf16s(const unsigned short* __restrict__ Ahi_, const unsigned short* __restrict__ Alo_,
                int lda, long long sA,
                const unsigned short* __restrict__ Bhi_, const unsigned short* __restrict__ Blo_,
                int ldb, long long sB,
                float* __restrict__ out, int ldc, long long sC, int coffC,
                int Ncols, int K, float alpha,
                const float* __restrict__ bias,
                const float* __restrict__ resid, int ldres,
                int ksplit, float* __restrict__ part, long long partStride)
{
    constexpr uint32_t STG = 49152;
    constexpr uint32_t AHI = 0, ALO = 16384, BHI = 32768, BLO = 40960;
    extern __shared__ char sm[];
    const uint32_t sbase = smem_u32(sm);

    const int z = blockIdx.z / ksplit;
    const int kz = blockIdx.z - z * ksplit;
    const unsigned short* Ahi = Ahi_ + (long long)z * sA;
    const unsigned short* Alo = Alo_ + (long long)z * sA;
    const unsigned short* Bhi = Bhi_ + (long long)z * sB;
    const unsigned short* Blo = Blo_ + (long long)z * sB;
    const int chunks = (K >> 6) / ksplit;
    const int koff = kz * chunks * 64;
    float* optr = part ? (part + (long long)kz * partStride + (long long)z * sC + (long long)z * coffC)
                       : (out + (long long)z * sC + (long long)z * coffC);

    const int tid = threadIdx.x;
    const int lane = tid & 31;
    const int wid = tid >> 5;
    const int wm = wid >> 1;
    const int wn = wid & 1;
    const int m0 = blockIdx.y * 128;
    const int n0 = blockIdx.x * 64;

    const uint32_t xorv = (uint32_t)(lane & 7) << 4;
    const uint32_t a_cg = (uint32_t)(lane >> 4) << 4;
    const uint32_t b_cg = (uint32_t)((lane >> 3) & 1) << 4;
    uint32_t arow[2], brow[2];
    #pragma unroll
    for (int mt = 0; mt < 2; mt++)
        arow[mt] = (uint32_t)(wm * 32 + mt * 16 + (lane & 15)) * 128;
    const int b_r = wn * 32 + (lane & 7) + ((lane >> 4) * 8);
    #pragma unroll
    for (int nt = 0; nt < 2; nt++)
        brow[nt] = (uint32_t)(b_r + nt * 16) * 128;

    const int srow = tid >> 3;
    const int sc16 = tid & 7;
    const uint32_t soff_base = (uint32_t)(sc16 * 16);

    float acc[2][4][4] = {};

    #define STAGE(SB, K0) do {                                                        \
        uint32_t base = sbase + (uint32_t)(SB) * STG;                                 \
        _Pragma("unroll")                                                             \
        for (int s = 0; s < 4; s++) {                                                 \
            int row = srow + s * 32;                                                  \
            uint32_t off = (uint32_t)row * 128 + (soff_base ^ (((uint32_t)row & 7) << 4)); \
            cp16(base + AHI + off, Ahi + (size_t)(m0 + row) * lda + (K0) + sc16 * 8); \
            cp16(base + ALO + off, Alo + (size_t)(m0 + row) * lda + (K0) + sc16 * 8); \
        }                                                                             \
        _Pragma("unroll")                                                             \
        for (int s = 0; s < 2; s++) {                                                 \
            int row = srow + s * 32;                                                  \
            uint32_t off = (uint32_t)row * 128 + (soff_base ^ (((uint32_t)row & 7) << 4)); \
            cp16(base + BHI + off, Bhi + (size_t)(n0 + row) * ldb + (K0) + sc16 * 8); \
            cp16(base + BLO + off, Blo + (size_t)(n0 + row) * ldb + (K0) + sc16 * 8); \
        }                                                                             \
    } while (0)

    STAGE(0, koff);
    CP_COMMIT();

    #pragma unroll 1
    for (int c = 0; c < chunks; c++) {
        if (c < chunks - 1) { STAGE((c + 1) & 1, koff + (c + 1) * 64); CP_COMMIT(); CP_WAIT1(); }
        else                { CP_WAIT0(); }
        __syncthreads();

        const uint32_t stg = sbase + (uint32_t)(c & 1) * STG;
        #pragma unroll
        for (int kk = 0; kk < 4; kk++) {
            const uint32_t cbA = (((uint32_t)kk << 5) | a_cg) ^ xorv;
            const uint32_t cbB = (((uint32_t)kk << 5) | b_cg) ^ xorv;
            uint32_t ah0[4], ah1[4], al0[4], al1[4];
            uint32_t bh0[4], bh1[4], bl0[4], bl1[4];
            ldsm_x4(ah0, stg + AHI + arow[0] + cbA);
            ldsm_x4(ah1, stg + AHI + arow[1] + cbA);
            ldsm_x4(bh0, stg + BHI + brow[0] + cbB);
            ldsm_x4(bh1, stg + BHI + brow[1] + cbB);
            ldsm_x4(al0, stg + ALO + arow[0] + cbA);
            ldsm_x4(al1, stg + ALO + arow[1] + cbA);
            ldsm_x4(bl0, stg + BLO + brow[0] + cbB);
            ldsm_x4(bl1, stg + BLO + brow[1] + cbB);
            mma16816(acc[0][0], ah0, &bh0[0]);
            mma16816(acc[0][1], ah0, &bh0[2]);
            mma16816(acc[0][2], ah0, &bh1[0]);
            mma16816(acc[0][3], ah0, &bh1[2]);
            mma16816(acc[1][0], ah1, &bh0[0]);
            mma16816(acc[1][1], ah1, &bh0[2]);
            mma16816(acc[1][2], ah1, &bh1[0]);
            mma16816(acc[1][3], ah1, &bh1[2]);
            mma16816(acc[0][0], ah0, &bl0[0]);
            mma16816(acc[0][1], ah0, &bl0[2]);
            mma16816(acc[0][2], ah0, &bl1[0]);
            mma16816(acc[0][3], ah0, &bl1[2]);
            mma16816(acc[1][0], ah1, &bl0[0]);
            mma16816(acc[1][1], ah1, &bl0[2]);
            mma16816(acc[1][2], ah1, &bl1[0]);
            mma16816(acc[1][3], ah1, &bl1[2]);
            mma16816(acc[0][0], al0, &bh0[0]);
            mma16816(acc[0][1], al0, &bh0[2]);
            mma16816(acc[0][2], al0, &bh1[0]);
            mma16816(acc[0][3], al0, &bh1[2]);
            mma16816(acc[1][0], al1, &bh0[0]);
            mma16816(acc[1][1], al1, &bh0[2]);
            mma16816(acc[1][2], al1, &bh1[0]);
            mma16816(acc[1][3], al1, &bh1[2]);
        }
        __syncthreads();
    }

    #pragma unroll
    for (int mt = 0; mt < 2; mt++) {
        #pragma unroll
        for (int nt = 0; nt < 4; nt++) {
            int row = m0 + wm * 32 + mt * 16 + (lane >> 2);
            int col = n0 + wn * 32 + nt * 8 + (lane & 3) * 2;
            if (col >= Ncols) continue;
            #pragma unroll
            for (int half = 0; half < 2; half++) {
                int r = row + half * 8;
                float v0 = acc[mt][nt][half * 2 + 0] * alpha;
                float v1 = acc[mt][nt][half * 2 + 1] * alpha;
                if (!part) {
                    if (bias) { v0 += bias[r]; v1 += bias[r]; }
                    if (resid) {
                        float2 rr = *(const float2*)(resid + (size_t)r * ldres + col);
                        v0 += rr.x; v1 += rr.y;
                    }
                }
                *(float2*)(optr + (size_t)r * ldc + col) = make_float2(v0, v1);
            }
        }
    }
    #undef STAGE
}

// PV split-K finalize: ath/atl = split(sum of 4 partials), layout (1024, 512)
__global__ void pv_fin(const float* __restrict__ part,
                       unsigned short* __restrict__ hi, unsigned short* __restrict__ lo)
{
    int idx = blockIdx.x * blockDim.x + threadIdx.x;
    if (idx >= 1024 * 512) return;
    float v = part[idx] + part[524288 + idx] + part[2 * 524288 + idx] + part[3 * 524288 + idx];
    split_store(v, hi, lo, (size_t)idx);
}

// ---------------- softmax (one warp per row) -> split bf16 output -------------
__global__ void softmax_split(float* __restrict__ S,
                              unsigned short* __restrict__ hi, unsigned short* __restrict__ lo,
                              int rows, int cols)
{
    int warp = (blockIdx.x * blockDim.x + threadIdx.x) >> 5;
    int lane = threadIdx.x & 31;
    if (warp >= rows) return;
    float* row = S + (long long)warp * cols;
    unsigned short* ho = hi + (long long)warp * cols;
    unsigned short* lo_ = lo + (long long)warp * cols;
    float mx = -INFINITY;
    for (int i = lane; i < cols; i += 32) mx = fmaxf(mx, row[i]);
    #pragma unroll
    for (int o = 16; o; o >>= 1) mx = fmaxf(mx, __shfl_xor_sync(0xffffffffu, mx, o));
    float sum = 0.f;
    for (int i = lane; i < cols; i += 32) {
        float e = __expf(row[i] - mx);
        row[i] = e;
        sum += e;
    }
    #pragma unroll
    for (int o = 16; o; o >>= 1) sum += __shfl_xor_sync(0xffffffffu, sum, o);
    float inv = 1.f / sum;
    for (int i = lane; i < cols; i += 32) {
        float v = row[i] * inv;
        __nv_bfloat16 h = __float2bfloat16(v);
        __nv_bfloat16 l = __float2bfloat16(v - __bfloat162float(h));
        ho[i] = *reinterpret_cast<unsigned short*>(&h);
        lo_[i] = *reinterpret_cast<unsigned short*>(&l);
    }
}

// ---------------- BEV grid transform ------------------------------------------
__global__ void grid_sample_kernel(const float* __restrict__ in, float* __restrict__ out)
{
    int idx = blockIdx.x * blockDim.x + threadIdx.x;
    if (idx >= 512 * 50 * 50) return;
    int i = idx % 50;
    int j = (idx / 50) % 50;
    int c = idx / 2500;
    int iy = __float2int_rn(0.625f * (float)j + 0.1875f);
    int ix = __float2int_rn(0.625f * (float)i + 0.1875f);
    out[idx] = in[c * 1024 + iy * 32 + ix];
}

// ---------------- pixel shuffle r=2 -------------------------------------------
__global__ void pixel_shuffle_kernel(const float* __restrict__ in, float* __restrict__ out)
{
    int idx = blockIdx.x * blockDim.x + threadIdx.x;
    if (idx >= 512 * 100 * 100) return;
    int ox = idx % 100;
    int oy = (idx / 100) % 100;
    int c = idx / 10000;
    int y = oy >> 1, ry = oy & 1;
    int x = ox >> 1, rx = ox & 1;
    out[idx] = in[(c * 4 + ry * 2 + rx) * 2500 + y * 50 + x];
}

// ---------------- final 1x1 conv (512 -> 6) + sigmoid -------------------------
__global__ void conv1x1_sigmoid_kernel(
    const float* __restrict__ in, const float* __restrict__ w,
    const float* __restrict__ b, float* __restrict__ out)
{
    int idx = blockIdx.x * blockDim.x + threadIdx.x;
    if (idx >= 6 * 10000) return;
    int p = idx % 10000;
    int cls = idx / 10000;
    float acc = b[cls];
    const float* wp = w + cls * 512;
    #pragma unroll 4
    for (int c = 0; c < 512; c++)
        acc = fmaf(in[c * 10000 + p], wp[c], acc);
    out[idx] = 1.f / (1.f + __expf(-acc));
}

__global__ void copy_kernel(const float* __restrict__ in, float* __restrict__ out, int n)
{
    int i = blockIdx.x * blockDim.x + threadIdx.x;
    if (i < n) out[i] = in[i];
}

// ---------------- host orchestration -----------------------------------------
struct ConvCtx {
    unsigned short *whi, *wlo, *achi, *aclo;
    float* part;
};

static void conv_tc(const ConvCtx& cx, const float* in, long long woff, float* out,
                    int Co, int H, int W,
                    const float* bias,
                    const float* g, const float* bb, const float* m, const float* v,
                    const float* res, int relu)
{
    int P = H * W;
    tsplit_kernel<<<dim3((P + 31) / 32, 16, 1), dim3(32, 8)>>>(in, 512, P, 0,
                                                               cx.achi, cx.aclo, 0);
    bool doSplit = (P == 2500 && Co == 512 && !g);   // BN layers are 100x100 anyway
    if (doSplit) {
        dim3 grid((unsigned)((P + 63) / 64), (unsigned)(Co / 128), 2);
        gemm_conv<<<grid, 256, 98304>>>(cx.whi + woff, cx.wlo + woff, cx.achi, cx.aclo,
                                        H, W, nullptr, Co, P, nullptr,
                                        nullptr, nullptr, nullptr, nullptr, nullptr, 0,
                                        36, cx.part);
        conv_fin<<<(512 * P + 255) / 256, 256>>>(cx.part, out, P, bias, res, relu);
    } else {
        dim3 grid((unsigned)((P + 63) / 64), (unsigned)(Co / 128), 1);
        gemm_conv<<<grid, 256, 98304>>>(cx.whi + woff, cx.wlo + woff, cx.achi, cx.aclo,
                                        H, W, out, Co, P, bias, g, bb, m, v, res, relu,
                                        72, nullptr);
    }
}

extern "C" void kernel_launch(void* const* d_in, const int* in_sizes, int n_in,
                              void* d_out, int out_size)
{
    const float* x       = (const float*)d_in[0];
    const float* qkv_w   = (const float*)d_in[1];
    const float* proj_w  = (const float*)d_in[2];
    const float* proj_b  = (const float*)d_in[3];
    const float* head_w  = (const float*)d_in[4];
    const float* head_b  = (const float*)d_in[5];
    const float* body_w  = (const float*)d_in[6];
    const float* body_b  = (const float*)d_in[7];
    const float* btail_w = (const float*)d_in[8];
    const float* btail_b = (const float*)d_in[9];
    const float* up_w    = (const float*)d_in[10];
    const float* up_b    = (const float*)d_in[11];
    const float* tail_w  = (const float*)d_in[12];
    const float* tail_b  = (const float*)d_in[13];
    const float* c1_w    = (const float*)d_in[14];
    const float* bn1_g   = (const float*)d_in[15];
    const float* bn1_b   = (const float*)d_in[16];
    const float* bn1_m   = (const float*)d_in[17];
    const float* bn1_v   = (const float*)d_in[18];
    const float* c2_w    = (const float*)d_in[19];
    const float* bn2_g   = (const float*)d_in[20];
    const float* bn2_b   = (const float*)d_in[21];
    const float* bn2_m   = (const float*)d_in[22];
    const float* bn2_v   = (const float*)d_in[23];
    const float* c3_w    = (const float*)d_in[24];
    const float* c3_b    = (const float*)d_in[25];

    float *gx, *gqkv, *gS, *gh, *b0, *b1, *b2, *gpart;
    cudaGetSymbolAddress((void**)&gx,    g_x);
    cudaGetSymbolAddress((void**)&gqkv,  g_qkv);
    cudaGetSymbolAddress((void**)&gS,    g_S);
    cudaGetSymbolAddress((void**)&gh,    g_h);
    cudaGetSymbolAddress((void**)&b0,    g_b0);
    cudaGetSymbolAddress((void**)&b1,    g_b1);
    cudaGetSymbolAddress((void**)&b2,    g_b2);
    cudaGetSymbolAddress((void**)&gpart, g_part);

    ConvCtx cx;
    cudaGetSymbolAddress((void**)&cx.whi,  g_whi);
    cudaGetSymbolAddress((void**)&cx.wlo,  g_wlo);
    cudaGetSymbolAddress((void**)&cx.achi, g_achi);
    cudaGetSymbolAddress((void**)&cx.aclo, g_aclo);
    cx.part = gpart;

    unsigned short *awh, *awl, *pwh, *pwl, *xth, *xtl, *qth, *qtl, *kth, *ktl;
    unsigned short *sh, *sl, *vh, *vl, *ath, *atl;
    cudaGetSymbolAddress((void**)&awh, g_awh);
    cudaGetSymbolAddress((void**)&awl, g_awl);
    cudaGetSymbolAddress((void**)&pwh, g_pwh);
    cudaGetSymbolAddress((void**)&pwl, g_pwl);
    cudaGetSymbolAddress((void**)&xth, g_xth);
    cudaGetSymbolAddress((void**)&xtl, g_xtl);
    cudaGetSymbolAddress((void**)&qth, g_qth);
    cudaGetSymbolAddress((void**)&qtl, g_qtl);
    cudaGetSymbolAddress((void**)&kth, g_kth);
    cudaGetSymbolAddress((void**)&ktl, g_ktl);
    cudaGetSymbolAddress((void**)&sh,  g_sh);
    cudaGetSymbolAddress((void**)&sl,  g_sl);
    cudaGetSymbolAddress((void**)&vh,  g_vh);
    cudaGetSymbolAddress((void**)&vl,  g_vl);
    cudaGetSymbolAddress((void**)&ath, g_ath);
    cudaGetSymbolAddress((void**)&atl, g_atl);

    cudaFuncSetAttribute(gemm_bf16s, cudaFuncAttributeMaxDynamicSharedMemorySize, 98304);
    cudaFuncSetAttribute(gemm_conv,  cudaFuncAttributeMaxDynamicSharedMemorySize, 98304);

    // ---- conv weight pre-split with tap-major K permutation ----
    {
        auto ws = [&](const float* src, long long off, int rows) {
            wsplit_perm<<<dim3(18, (unsigned)rows), 256>>>(src, cx.whi + off, cx.wlo + off);
        };
        ws(head_w,  0,                 512);
        ws(body_w,  (long long)1 * LW, 16 * 512);
        ws(btail_w, (long long)17 * LW, 512);
        ws(up_w,    (long long)18 * LW, 2048);
        ws(tail_w,  (long long)22 * LW, 512);
        ws(c1_w,    (long long)23 * LW, 512);
        ws(c2_w,    (long long)24 * LW, 512);
    }
    // ---- attention weight transpose-splits (batched over 8 blocks) ----
    {
        dim3 blk(32, 8);
        tsplit_kernel<<<dim3(48, 16, 8), blk>>>(qkv_w, 512, 1536, 512LL * 1536,
                                                awh, awl, 1536LL * 512);
        tsplit_kernel<<<dim3(16, 16, 8), blk>>>(proj_w, 512, 512, 512LL * 512,
                                                pwh, pwl, 512LL * 512);
    }

    copy_kernel<<<(512 * 1024 + 255) / 256, 256>>>(x, gx, 512 * 1024);

    const float scale = 0.044194173824159216f;  // 512^-0.5
    dim3 blk32(32, 8);

    // ---- 8 self-attention blocks (MMA path) ----
    for (int i = 0; i < 8; i++) {
        tsplit_kernel<<<dim3(32, 16, 1), blk32>>>(gx, 512, 1024, 0, xth, xtl, 0);
        gemm_bf16s<<<dim3(16, 12, 1), 256, 98304>>>(
            awh + (long long)i * 1536 * 512, awl + (long long)i * 1536 * 512, 512, 0,
            xth, xtl, 512, 0,
            gqkv, 1024, 0, 0, 1024, 512, 1.f, nullptr, nullptr, 0,
            1, nullptr, 0);
        tsplit_kernel<<<dim3(32, 16, 1), blk32>>>(gqkv, 512, 1024, 0, qth, qtl, 0);
        tsplit_kernel<<<dim3(32, 16, 1), blk32>>>(gqkv + 512 * 1024, 512, 1024, 0, kth, ktl, 0);
        gemm_bf16s<<<dim3(16, 8, 8), 256, 98304>>>(
            qth, qtl, 512, 64,
            kth, ktl, 512, 64,
            gS, 1024, 1024LL * 1024, 0, 1024, 64, scale, nullptr, nullptr, 0,
            1, nullptr, 0);
        softmax_split<<<1024, 256>>>(gS, sh, sl, 8 * 1024, 1024);
        wsplit_kernel<<<(512 * 1024 + 255) / 256, 256>>>(gqkv + 1024 * 1024, vh, vl, 512 * 1024);
        // PV: split-K x4 -> 256 CTAs; finalize fuses the 4-way sum + bf16 split
        gemm_bf16s<<<dim3(1, 8, 32), 256, 98304>>>(
            sh, sl, 1024, 1024LL * 1024,
            vh, vl, 1024, 64LL * 1024,
            nullptr, 512, 0, 64, 64, 1024, 1.f, nullptr, nullptr, 0,
            4, gpart, 524288);
        pv_fin<<<(1024 * 512 + 255) / 256, 256>>>(gpart, ath, atl);
        gemm_bf16s<<<dim3(16, 4, 1), 256, 98304>>>(
            pwh + (long long)i * 512 * 512, pwl + (long long)i * 512 * 512, 512, 0,
            ath, atl, 512, 0,
            gx, 1024, 0, 0, 1024, 512, 1.f,
            proj_b + i * 512, gx, 1024,
            1, nullptr, 0);
    }

    // ---- BEV grid transform ----
    grid_sample_kernel<<<(512 * 2500 + 255) / 256, 256>>>(gx, b0);

    // ---- EDSR (split-K bf16 convs on 50x50) ----
    conv_tc(cx, b0, 0, gh, 512, 50, 50, head_b, 0, 0, 0, 0, nullptr, 0);
    const float* rcur = gh;
    float* bufs[2] = {b1, b2};
    for (int i = 0; i < 8; i++) {
        long long w0 = (long long)(1 + 2 * i) * LW;
        long long w1 = (long long)(2 + 2 * i) * LW;
        conv_tc(cx, rcur, w0, b0, 512, 50, 50, body_b + i * 1024, 0, 0, 0, 0, nullptr, 1);
        float* rnext = bufs[i & 1];
        conv_tc(cx, b0, w1, rnext, 512, 50, 50, body_b + i * 1024 + 512, 0, 0, 0, 0, rcur, 0);
        rcur = rnext;
    }
    conv_tc(cx, rcur, (long long)17 * LW, b1, 512, 50, 50, btail_b, 0, 0, 0, 0, gh, 0);
    conv_tc(cx, b1, (long long)18 * LW, b2, 2048, 50, 50, up_b, 0, 0, 0, 0, nullptr, 0);
    pixel_shuffle_kernel<<<(512 * 10000 + 255) / 256, 256>>>(b2, b0);
    conv_tc(cx, b0, (long long)22 * LW, b1, 512, 100, 100, tail_b, 0, 0, 0, 0, nullptr, 0);

    // ---- classifier ----
    conv_tc(cx, b1, (long long)23 * LW, b0, 512, 100, 100, nullptr, bn1_g, bn1_b, bn1_m, bn1_v, nullptr, 1);
    conv_tc(cx, b0, (long long)24 * LW, b1, 512, 100, 100, nullptr, bn2_g, bn2_b, bn2_m, bn2_v, nullptr, 1);
    conv1x1_sigmoid_kernel<<<(6 * 10000 + 255) / 256, 256>>>(b1, c3_w, c3_b, (float*)d_out);
}